// round 6
// baseline (speedup 1.0000x reference)
#include <cuda_runtime.h>
#include <cuda_bf16.h>
#include <math.h>
#include <stdint.h>

#define HID   2048
#define NB    2
#define SQ    2048
#define NHEAD 16
#define HD    128
#define MROWS (NB * SQ)        /* 4096 */
#define NW    (HID * HID)      /* 4194304 */
#define KDIM  2048

/* ---------------- scratch (device globals; no allocation allowed) -------- */
__device__ __nv_bfloat16 g_Wh[4][NW];
__device__ __nv_bfloat16 g_Wl[4][NW];
__device__ __nv_bfloat16 g_Xh[MROWS * HID];
__device__ __nv_bfloat16 g_Xl[MROWS * HID];
__device__ __nv_bfloat16 g_Ah[MROWS * HID];
__device__ __nv_bfloat16 g_Al[MROWS * HID];
__device__ float g_Q[MROWS * HID];
__device__ float g_K[MROWS * HID];
__device__ float g_V[MROWS * HID];

__device__ __forceinline__ uint32_t smem_u32(const void* p) {
    uint32_t a;
    asm("{ .reg .u64 t; cvta.to.shared.u64 t, %1; cvt.u32.u64 %0, t; }"
        : "=r"(a) : "l"(p));
    return a;
}
__device__ __forceinline__ void ldm_x4(uint32_t* r, uint32_t addr) {
    asm volatile("ldmatrix.sync.aligned.m8n8.x4.shared.b16 {%0,%1,%2,%3}, [%4];"
                 : "=r"(r[0]), "=r"(r[1]), "=r"(r[2]), "=r"(r[3]) : "r"(addr));
}
__device__ __forceinline__ void mma_bf16(float* d, const uint32_t* a,
                                         uint32_t b0, uint32_t b1) {
    asm volatile("mma.sync.aligned.m16n8k16.row.col.f32.bf16.bf16.f32 "
                 "{%0,%1,%2,%3},{%4,%5,%6,%7},{%8,%9},{%0,%1,%2,%3};"
                 : "+f"(d[0]), "+f"(d[1]), "+f"(d[2]), "+f"(d[3])
                 : "r"(a[0]), "r"(a[1]), "r"(a[2]), "r"(a[3]), "r"(b0), "r"(b1));
}
__device__ __forceinline__ void split4(float4 v, uint2& hi, uint2& lo) {
    __nv_bfloat162 h0 = __float22bfloat162_rn(make_float2(v.x, v.y));
    __nv_bfloat162 h1 = __float22bfloat162_rn(make_float2(v.z, v.w));
    float2 f0 = __bfloat1622float2(h0), f1 = __bfloat1622float2(h1);
    __nv_bfloat162 l0 = __float22bfloat162_rn(make_float2(v.x - f0.x, v.y - f0.y));
    __nv_bfloat162 l1 = __float22bfloat162_rn(make_float2(v.z - f1.x, v.w - f1.y));
    hi = make_uint2(*(uint32_t*)&h0, *(uint32_t*)&h1);
    lo = make_uint2(*(uint32_t*)&l0, *(uint32_t*)&l1);
}
__device__ __forceinline__ uint32_t pack_hi(float a, float b) {
    __nv_bfloat162 h = __float22bfloat162_rn(make_float2(a, b));
    return *(uint32_t*)&h;
}
__device__ __forceinline__ uint32_t pack_lo(float a, float b, uint32_t hi) {
    float2 f = __bfloat1622float2(*(__nv_bfloat162*)&hi);
    __nv_bfloat162 l = __float22bfloat162_rn(make_float2(a - f.x, b - f.y));
    return *(uint32_t*)&l;
}
__device__ __forceinline__ void cp16(uint32_t smem, const void* g) {
    asm volatile("cp.async.cg.shared.global [%0], [%1], 16;"
                 :: "r"(smem), "l"(g) : "memory");
}
__device__ __forceinline__ void cp_commit() {
    asm volatile("cp.async.commit_group;" ::: "memory");
}
template <int N>
__device__ __forceinline__ void cp_wait() {
    asm volatile("cp.async.wait_group %0;" :: "n"(N) : "memory");
}

/* ---------------- weight reconstruction -> bf16 hi/lo -------------------- */
__global__ void build_weights(const float* __restrict__ cpq,
                              const float* __restrict__ cpk,
                              const float* __restrict__ cpv,
                              const float* __restrict__ cpo,
                              int ncp) {
    int i = blockIdx.x * 256 + threadIdx.x;
    if (i >= NW) return;
    const float dT = 1.0f / (float)(NW - 1);
    const float dX = 1.0f / (float)(ncp - 1);
    float t = (float)i * dT;
    int j = (int)((double)t * (double)(ncp - 1));
    if (j > ncp - 2) j = ncp - 2;
    if (j < 0) j = 0;
    while (j < ncp - 2 && (float)(j + 1) * dX <= t) j++;
    while (j > 0 && (float)j * dX > t) j--;
    float x0 = (float)j * dX;
    float x1 = (float)(j + 1) * dX;
    float f  = (t - x0) / (x1 - x0);
    const float* cps[4] = {cpq, cpk, cpv, cpo};
#pragma unroll
    for (int w = 0; w < 4; w++) {
        float a = cps[w][j];
        float val = fmaf(cps[w][j + 1] - a, f, a);
        __nv_bfloat16 hb = __float2bfloat16_rn(val);
        g_Wh[w][i] = hb;
        g_Wl[w][i] = __float2bfloat16_rn(val - __bfloat162float(hb));
    }
}

/* ---------------- split hidden_states -> bf16 hi/lo ---------------------- */
__global__ void split_x(const float* __restrict__ x) {
    int i = blockIdx.x * 256 + threadIdx.x;       /* float4 index */
    if (i >= MROWS * HID / 4) return;
    float4 v = *(const float4*)(x + 4 * (size_t)i);
    uint2 hi, lo; split4(v, hi, lo);
    *(uint2*)(g_Xh + 4 * (size_t)i) = hi;
    *(uint2*)(g_Xl + 4 * (size_t)i) = lo;
}

/* =============== bf16x3 HMMA GEMM (pre-split, cp.async x3) =============== */
/* C[M,2048] = A*B^T from Ah/Al [M,K], Bh/Bl [N,K] bf16. CTA 128x128.       */
#define KC      32
#define NCHUNK  (KDIM / KC)
#define SA      40                      /* halfwords per smem row (80 B)    */
#define TILE_HW (128 * SA)
#define TILE_B  (TILE_HW * 2)           /* 10240 B                          */
#define STG_B   (4 * TILE_B)            /* Ah, Al, Bh, Bl: 40960 B          */
#define NSTAGE  3
#define GEMM_SMEM (NSTAGE * STG_B)      /* 122880 B                         */

__global__ void __launch_bounds__(512) gemm_hmma(const __nv_bfloat16* __restrict__ Ah,
                                                 const __nv_bfloat16* __restrict__ Al,
                                                 const __nv_bfloat16* __restrict__ Bh,
                                                 const __nv_bfloat16* __restrict__ Bl,
                                                 float* __restrict__ C) {
    extern __shared__ char shg[];
    const uint32_t sb = smem_u32(shg);
    const int tid = threadIdx.x;
    const int lane = tid & 31, wid = tid >> 5;
    const int warp_m = wid >> 2, warp_n = wid & 3;
    const int m0 = blockIdx.y * 128, n0 = blockIdx.x * 128;

    /* cp.async coords: each thread copies one 16B chunk per tile per stage */
    const int rC = tid >> 2;                 /* 0..127 row                   */
    const int cC = (tid & 3) << 3;           /* bf16 col: 0,8,16,24          */
    const __nv_bfloat16* gA[2] = {Ah + (size_t)(m0 + rC) * KDIM + cC,
                                  Al + (size_t)(m0 + rC) * KDIM + cC};
    const __nv_bfloat16* gB[2] = {Bh + (size_t)(n0 + rC) * KDIM + cC,
                                  Bl + (size_t)(n0 + rC) * KDIM + cC};
    const uint32_t sdst = sb + (uint32_t)(rC * SA + cC) * 2;

    float acc[2][4][4];
#pragma unroll
    for (int i = 0; i < 2; i++)
#pragma unroll
        for (int j = 0; j < 4; j++)
#pragma unroll
            for (int q = 0; q < 4; q++) acc[i][j][q] = 0.0f;

    const int rowA = lane & 15, colA8 = (lane >= 16) ? 8 : 0;
    const int rowB = (lane & 7) + ((lane >= 16) ? 8 : 0);
    const int colB8 = (lane & 8) ? 8 : 0;
    const uint32_t aoff = (uint32_t)((warp_m * 32 + rowA) * SA + colA8) * 2;
    const uint32_t boff = (uint32_t)((warp_n * 32 + rowB) * SA + colB8) * 2;

    /* prologue: issue stages 0..NSTAGE-2 */
#pragma unroll
    for (int p = 0; p < NSTAGE - 1; p++) {
        uint32_t d = sdst + p * STG_B;
        cp16(d + 0 * TILE_B, gA[0] + p * KC);
        cp16(d + 1 * TILE_B, gA[1] + p * KC);
        cp16(d + 2 * TILE_B, gB[0] + p * KC);
        cp16(d + 3 * TILE_B, gB[1] + p * KC);
        cp_commit();
    }

    int stage = 0;
    for (int c = 0; c < NCHUNK; c++) {
        if (c < NCHUNK - 1) cp_wait<1>(); else cp_wait<0>();
        __syncthreads();

        const uint32_t tAh = sb + stage * STG_B;
        const uint32_t tAl = tAh + TILE_B;
        const uint32_t tBh = tAh + 2 * TILE_B;
        const uint32_t tBl = tAh + 3 * TILE_B;
#pragma unroll
        for (int ks = 0; ks < 2; ks++) {
            const uint32_t ksoff = (uint32_t)(ks * 16) * 2;
            uint32_t ah[2][4], al[2][4], bh[2][4], bl[2][4];
#pragma unroll
            for (int mt = 0; mt < 2; mt++) {
                ldm_x4(ah[mt], tAh + aoff + ksoff + (uint32_t)(mt * 16 * SA) * 2);
                ldm_x4(al[mt], tAl + aoff + ksoff + (uint32_t)(mt * 16 * SA) * 2);
            }
#pragma unroll
            for (int g = 0; g < 2; g++) {
                ldm_x4(bh[g], tBh + boff + ksoff + (uint32_t)(g * 16 * SA) * 2);
                ldm_x4(bl[g], tBl + boff + ksoff + (uint32_t)(g * 16 * SA) * 2);
            }
#pragma unroll
            for (int mt = 0; mt < 2; mt++)
#pragma unroll
                for (int nt = 0; nt < 4; nt++) {
                    int g = nt >> 1, p = (nt & 1) * 2;
                    mma_bf16(acc[mt][nt], ah[mt], bh[g][p], bh[g][p + 1]);
                    mma_bf16(acc[mt][nt], ah[mt], bl[g][p], bl[g][p + 1]);
                    mma_bf16(acc[mt][nt], al[mt], bh[g][p], bh[g][p + 1]);
                }
        }

        /* issue chunk c + NSTAGE-1 into this (just-freed predecessor) slot */
        int cn = c + NSTAGE - 1;
        if (cn < NCHUNK) {
            uint32_t d = sdst + ((cn % NSTAGE) * STG_B);
            int kc = cn * KC;
            cp16(d + 0 * TILE_B, gA[0] + kc);
            cp16(d + 1 * TILE_B, gA[1] + kc);
            cp16(d + 2 * TILE_B, gB[0] + kc);
            cp16(d + 3 * TILE_B, gB[1] + kc);
            cp_commit();
        }
        stage = (stage + 1 == NSTAGE) ? 0 : stage + 1;
    }

    const int rowg = lane >> 2, colg = (lane & 3) * 2;
#pragma unroll
    for (int mt = 0; mt < 2; mt++) {
#pragma unroll
        for (int nt = 0; nt < 4; nt++) {
            int r = m0 + warp_m * 32 + mt * 16 + rowg;
            int cc = n0 + warp_n * 32 + nt * 8 + colg;
            *(float2*)(C + (size_t)r * KDIM + cc) =
                make_float2(acc[mt][nt][0], acc[mt][nt][1]);
            *(float2*)(C + (size_t)(r + 8) * KDIM + cc) =
                make_float2(acc[mt][nt][2], acc[mt][nt][3]);
        }
    }
}

/* ========== bf16x3 HMMA causal flash attention =========================== */
#define FKS 136
#define FVS 72
#define OFF_QH 0
#define OFF_QL (128 * FKS)
#define OFF_KH (2 * 128 * FKS)
#define OFF_KL (OFF_KH + 64 * FKS)
#define OFF_VH (OFF_KL + 64 * FKS)
#define OFF_VL (OFF_VH + 128 * FVS)
#define FL_SMEM ((OFF_VL + 128 * FVS) * 2)

__global__ void __launch_bounds__(256, 1) flash_hmma(const float* __restrict__ Q,
                                                     const float* __restrict__ Km,
                                                     const float* __restrict__ Vm) {
    extern __shared__ char shf[];
    __nv_bfloat16* s = (__nv_bfloat16*)shf;
    const uint32_t sb = smem_u32(shf);
    const int tid = threadIdx.x, lane = tid & 31, wid = tid >> 5;
    const int qb = blockIdx.x, h = blockIdx.y, b = blockIdx.z;
    const int q0 = qb * 128;
    const int wm0 = wid * 16;
    const float scale = 0.08838834764831845f;

    const float* Qg = Q + (size_t)(b * SQ + q0) * HID + h * HD;
#pragma unroll
    for (int it = 0; it < 16; it++) {
        int idx = tid + it * 256;
        int r = idx >> 5, c4 = (idx & 31) << 2;
        float4 v = *(const float4*)(Qg + (size_t)r * HID + c4);
        uint2 hi, lo; split4(v, hi, lo);
        *(uint2*)(s + OFF_QH + r * FKS + c4) = hi;
        *(uint2*)(s + OFF_QL + r * FKS + c4) = lo;
    }

    const uint32_t aBaseH = sb + 2u * (OFF_QH + (wm0 + (lane & 15)) * FKS + ((lane >> 4) << 3));
    const uint32_t aBaseL = sb + 2u * (OFF_QL + (wm0 + (lane & 15)) * FKS + ((lane >> 4) << 3));
    const int krow = (lane & 7) + ((lane >> 4) << 3);
    const uint32_t kBaseH = sb + 2u * (OFF_KH + krow * FKS + (lane & 8));
    const uint32_t kBaseL = sb + 2u * (OFF_KL + krow * FKS + (lane & 8));
    const uint32_t vBaseH = sb + 2u * (OFF_VH + krow * FVS + (lane & 8));
    const uint32_t vBaseL = sb + 2u * (OFF_VL + krow * FVS + (lane & 8));

    float acc_o[16][4];
#pragma unroll
    for (int i = 0; i < 16; i++)
#pragma unroll
        for (int j = 0; j < 4; j++) acc_o[i][j] = 0.0f;
    float m0r = -1e30f, m1r = -1e30f, l0r = 0.0f, l1r = 0.0f;

    const int kb_max = 2 * qb + 1;
    const int r0g = q0 + wm0 + (lane >> 2);
    const int r1g = r0g + 8;

    for (int kb = 0; kb <= kb_max; kb++) {
        const int k0 = kb * 64;
        __syncthreads();
        const float* Kg = Km + (size_t)(b * SQ + k0) * HID + h * HD;
#pragma unroll
        for (int it = 0; it < 8; it++) {
            int idx = tid + it * 256;
            int r = idx >> 5, c4 = (idx & 31) << 2;
            float4 v = *(const float4*)(Kg + (size_t)r * HID + c4);
            uint2 hi, lo; split4(v, hi, lo);
            *(uint2*)(s + OFF_KH + r * FKS + c4) = hi;
            *(uint2*)(s + OFF_KL + r * FKS + c4) = lo;
        }
        const float* Vg = Vm + (size_t)(b * SQ + k0) * HID + h * HD;
#pragma unroll
        for (int it = 0; it < 8; it++) {
            int idx = tid + it * 256;
            int r = idx & 63, c4 = (idx >> 6) << 2;
            float4 v = *(const float4*)(Vg + (size_t)r * HID + c4);
            float e[4] = {v.x, v.y, v.z, v.w};
#pragma unroll
            for (int q = 0; q < 4; q++) {
                __nv_bfloat16 hb = __float2bfloat16_rn(e[q]);
                __nv_bfloat16 lb = __float2bfloat16_rn(e[q] - __bfloat162float(hb));
                s[OFF_VH + (c4 + q) * FVS + r] = hb;
                s[OFF_VL + (c4 + q) * FVS + r] = lb;
            }
        }
        __syncthreads();

        if (k0 > q0 + wm0) continue;

        float accs[8][4];
#pragma unroll
        for (int i = 0; i < 8; i++)
#pragma unroll
            for (int j = 0; j < 4; j++) accs[i][j] = 0.0f;
#pragma unroll
        for (int ks = 0; ks < 8; ks++) {
            uint32_t ah[4], al[4];
            ldm_x4(ah, aBaseH + ks * 32);
            ldm_x4(al, aBaseL + ks * 32);
#pragma unroll
            for (int ng = 0; ng < 4; ng++) {
                uint32_t bh[4], bl[4];
                ldm_x4(bh, kBaseH + (uint32_t)(ng * 16 * FKS) * 2 + ks * 32);
                ldm_x4(bl, kBaseL + (uint32_t)(ng * 16 * FKS) * 2 + ks * 32);
                mma_bf16(accs[2 * ng],     ah, bh[0], bh[1]);
                mma_bf16(accs[2 * ng],     ah, bl[0], bl[1]);
                mma_bf16(accs[2 * ng],     al, bh[0], bh[1]);
                mma_bf16(accs[2 * ng + 1], ah, bh[2], bh[3]);
                mma_bf16(accs[2 * ng + 1], ah, bl[2], bl[3]);
                mma_bf16(accs[2 * ng + 1], al, bh[2], bh[3]);
            }
        }

#pragma unroll
        for (int nt = 0; nt < 8; nt++) {
            int cb = k0 + nt * 8 + (lane & 3) * 2;
            accs[nt][0] = accs[nt][0] * scale + ((cb     > r0g) ? -1e9f : 0.0f);
            accs[nt][1] = accs[nt][1] * scale + ((cb + 1 > r0g) ? -1e9f : 0.0f);
            accs[nt][2] = accs[nt][2] * scale + ((cb     > r1g) ? -1e9f : 0.0f);
            accs[nt][3] = accs[nt][3] * scale + ((cb + 1 > r1g) ? -1e9f : 0.0f);
        }

        float mx0 = -1e30f, mx1 = -1e30f;
#pragma unroll
        for (int nt = 0; nt < 8; nt++) {
            mx0 = fmaxf(mx0, fmaxf(accs[nt][0], accs[nt][1]));
            mx1 = fmaxf(mx1, fmaxf(accs[nt][2], accs[nt][3]));
        }
        mx0 = fmaxf(mx0, __shfl_xor_sync(0xffffffffu, mx0, 1));
        mx0 = fmaxf(mx0, __shfl_xor_sync(0xffffffffu, mx0, 2));
        mx1 = fmaxf(mx1, __shfl_xor_sync(0xffffffffu, mx1, 1));
        mx1 = fmaxf(mx1, __shfl_xor_sync(0xffffffffu, mx1, 2));
        float mn0 = fmaxf(m0r, mx0), mn1 = fmaxf(m1r, mx1);
        float al0 = __expf(m0r - mn0), al1 = __expf(m1r - mn1);
        m0r = mn0; m1r = mn1;
        float rs0 = 0.0f, rs1 = 0.0f;
#pragma unroll
        for (int nt = 0; nt < 8; nt++) {
            accs[nt][0] = __expf(accs[nt][0] - mn0);
            accs[nt][1] = __expf(accs[nt][1] - mn0);
            accs[nt][2] = __expf(accs[nt][2] - mn1);
            accs[nt][3] = __expf(accs[nt][3] - mn1);
            rs0 += accs[nt][0] + accs[nt][1];
            rs1 += accs[nt][2] + accs[nt][3];
        }
        rs0 += __shfl_xor_sync(0xffffffffu, rs0, 1);
        rs0 += __shfl_xor_sync(0xffffffffu, rs0, 2);
        rs1 += __shfl_xor_sync(0xffffffffu, rs1, 1);
        rs1 += __shfl_xor_sync(0xffffffffu, rs1, 2);
        l0r = l0r * al0 + rs0;
        l1r = l1r * al1 + rs1;
#pragma unroll
        for (int i = 0; i < 16; i++) {
            acc_o[i][0] *= al0; acc_o[i][1] *= al0;
            acc_o[i][2] *= al1; acc_o[i][3] *= al1;
        }

        uint32_t ph[4][4], pl[4][4];
#pragma unroll
        for (int kk = 0; kk < 4; kk++) {
            int n0t = 2 * kk, n1t = 2 * kk + 1;
            ph[kk][0] = pack_hi(accs[n0t][0], accs[n0t][1]);
            pl[kk][0] = pack_lo(accs[n0t][0], accs[n0t][1], ph[kk][0]);
            ph[kk][1] = pack_hi(accs[n0t][2], accs[n0t][3]);
            pl[kk][1] = pack_lo(accs[n0t][2], accs[n0t][3], ph[kk][1]);
            ph[kk][2] = pack_hi(accs[n1t][0], accs[n1t][1]);
            pl[kk][2] = pack_lo(accs[n1t][0], accs[n1t][1], ph[kk][2]);
            ph[kk][3] = pack_hi(accs[n1t][2], accs[n1t][3]);
            pl[kk][3] = pack_lo(accs[n1t][2], accs[n1t][3], ph[kk][3]);
        }

#pragma unroll
        for (int kk = 0; kk < 4; kk++) {
#pragma unroll
            for (int g = 0; g < 8; g++) {
                uint32_t vh[4], vl[4];
                ldm_x4(vh, vBaseH + (uint32_t)(g * 16 * FVS) * 2 + kk * 32);
                ldm_x4(vl, vBaseL + (uint32_t)(g * 16 * FVS) * 2 + kk * 32);
                mma_bf16(acc_o[2 * g],     ph[kk], vh[0], vh[1]);
                mma_bf16(acc_o[2 * g],     ph[kk], vl[0], vl[1]);
                mma_bf16(acc_o[2 * g],     pl[kk], vh[0], vh[1]);
                mma_bf16(acc_o[2 * g + 1], ph[kk], vh[2], vh[3]);
                mma_bf16(acc_o[2 * g + 1], ph[kk], vl[2], vl[3]);
                mma_bf16(acc_o[2 * g + 1], pl[kk], vh[2], vh[3]);
            }
        }
    }

    /* ---- epilogue: write attention output directly as bf16 hi/lo ---- */
    float inv0 = 1.0f / l0r, inv1 = 1.0f / l1r;
    size_t base0 = (size_t)(b * SQ + r0g) * HID + h * HD;
    size_t base1 = base0 + (size_t)8 * HID;
#pragma unroll
    for (int nto = 0; nto < 16; nto++) {
        int c = nto * 8 + (lane & 3) * 2;
        float v0 = acc_o[nto][0] * inv0, v1 = acc_o[nto][1] * inv0;
        uint32_t hw = pack_hi(v0, v1);
        *(uint32_t*)(g_Ah + base0 + c) = hw;
        *(uint32_t*)(g_Al + base0 + c) = pack_lo(v0, v1, hw);
        float v2 = acc_o[nto][2] * inv1, v3 = acc_o[nto][3] * inv1;
        hw = pack_hi(v2, v3);
        *(uint32_t*)(g_Ah + base1 + c) = hw;
        *(uint32_t*)(g_Al + base1 + c) = pack_lo(v2, v3, hw);
    }
}

/* ---------------- launcher ---------------------------------------------- */
extern "C" void kernel_launch(void* const* d_in, const int* in_sizes, int n_in,
                              void* d_out, int out_size) {
    (void)n_in; (void)out_size;
    const float* x   = (const float*)d_in[0];
    const float* cpq = (const float*)d_in[1];
    const float* cpk = (const float*)d_in[2];
    const float* cpv = (const float*)d_in[3];
    const float* cpo = (const float*)d_in[4];
    float* out = (float*)d_out;
    int ncp = in_sizes[1];

    __nv_bfloat16 *pWh, *pWl, *pXh, *pXl, *pAh, *pAl;
    float *pQ, *pK, *pV;
    cudaGetSymbolAddress((void**)&pWh, g_Wh);
    cudaGetSymbolAddress((void**)&pWl, g_Wl);
    cudaGetSymbolAddress((void**)&pXh, g_Xh);
    cudaGetSymbolAddress((void**)&pXl, g_Xl);
    cudaGetSymbolAddress((void**)&pAh, g_Ah);
    cudaGetSymbolAddress((void**)&pAl, g_Al);
    cudaGetSymbolAddress((void**)&pQ, g_Q);
    cudaGetSymbolAddress((void**)&pK, g_K);
    cudaGetSymbolAddress((void**)&pV, g_V);

    build_weights<<<(NW + 255) / 256, 256>>>(cpq, cpk, cpv, cpo, ncp);
    split_x<<<(MROWS * HID / 4 + 255) / 256, 256>>>(x);

    cudaFuncSetAttribute(gemm_hmma, cudaFuncAttributeMaxDynamicSharedMemorySize,
                         GEMM_SMEM);
    dim3 gg(HID / 128, MROWS / 128);
    gemm_hmma<<<gg, 512, GEMM_SMEM>>>(pXh, pXl, pWh + 0 * (size_t)NW, pWl + 0 * (size_t)NW, pQ);
    gemm_hmma<<<gg, 512, GEMM_SMEM>>>(pXh, pXl, pWh + 1 * (size_t)NW, pWl + 1 * (size_t)NW, pK);
    gemm_hmma<<<gg, 512, GEMM_SMEM>>>(pXh, pXl, pWh + 2 * (size_t)NW, pWl + 2 * (size_t)NW, pV);

    cudaFuncSetAttribute(flash_hmma, cudaFuncAttributeMaxDynamicSharedMemorySize,
                         FL_SMEM);
    flash_hmma<<<dim3(SQ / 128, NHEAD, NB), 256, FL_SMEM>>>(pQ, pK, pV);

    gemm_hmma<<<gg, 512, GEMM_SMEM>>>(pAh, pAl, pWh + 3 * (size_t)NW, pWl + 3 * (size_t)NW, out);
}

// round 7
// speedup vs baseline: 1.0279x; 1.0279x over previous
#include <cuda_runtime.h>
#include <cuda_bf16.h>
#include <math.h>
#include <stdint.h>

#define HID   2048
#define NB    2
#define SQ    2048
#define NHEAD 16
#define HD    128
#define MROWS (NB * SQ)        /* 4096 */
#define NW    (HID * HID)      /* 4194304 */
#define KDIM  2048

/* ---------------- scratch (device globals; no allocation allowed) -------- */
__device__ __nv_bfloat16 g_Wh[4][NW];
__device__ __nv_bfloat16 g_Wl[4][NW];
__device__ __nv_bfloat16 g_Xh[MROWS * HID];
__device__ __nv_bfloat16 g_Xl[MROWS * HID];
__device__ __nv_bfloat16 g_Ah[MROWS * HID];
__device__ __nv_bfloat16 g_Al[MROWS * HID];
__device__ float g_Q[MROWS * HID];
__device__ float g_K[MROWS * HID];
__device__ float g_V[MROWS * HID];

__device__ __forceinline__ uint32_t smem_u32(const void* p) {
    uint32_t a;
    asm("{ .reg .u64 t; cvta.to.shared.u64 t, %1; cvt.u32.u64 %0, t; }"
        : "=r"(a) : "l"(p));
    return a;
}
__device__ __forceinline__ void ldm_x4(uint32_t* r, uint32_t addr) {
    asm volatile("ldmatrix.sync.aligned.m8n8.x4.shared.b16 {%0,%1,%2,%3}, [%4];"
                 : "=r"(r[0]), "=r"(r[1]), "=r"(r[2]), "=r"(r[3]) : "r"(addr));
}
__device__ __forceinline__ void mma_bf16(float* d, const uint32_t* a,
                                         uint32_t b0, uint32_t b1) {
    asm volatile("mma.sync.aligned.m16n8k16.row.col.f32.bf16.bf16.f32 "
                 "{%0,%1,%2,%3},{%4,%5,%6,%7},{%8,%9},{%0,%1,%2,%3};"
                 : "+f"(d[0]), "+f"(d[1]), "+f"(d[2]), "+f"(d[3])
                 : "r"(a[0]), "r"(a[1]), "r"(a[2]), "r"(a[3]), "r"(b0), "r"(b1));
}
__device__ __forceinline__ void split4(float4 v, uint2& hi, uint2& lo) {
    __nv_bfloat162 h0 = __float22bfloat162_rn(make_float2(v.x, v.y));
    __nv_bfloat162 h1 = __float22bfloat162_rn(make_float2(v.z, v.w));
    float2 f0 = __bfloat1622float2(h0), f1 = __bfloat1622float2(h1);
    __nv_bfloat162 l0 = __float22bfloat162_rn(make_float2(v.x - f0.x, v.y - f0.y));
    __nv_bfloat162 l1 = __float22bfloat162_rn(make_float2(v.z - f1.x, v.w - f1.y));
    hi = make_uint2(*(uint32_t*)&h0, *(uint32_t*)&h1);
    lo = make_uint2(*(uint32_t*)&l0, *(uint32_t*)&l1);
}
__device__ __forceinline__ uint32_t pack_hi(float a, float b) {
    __nv_bfloat162 h = __float22bfloat162_rn(make_float2(a, b));
    return *(uint32_t*)&h;
}
__device__ __forceinline__ uint32_t pack_lo(float a, float b, uint32_t hi) {
    float2 f = __bfloat1622float2(*(__nv_bfloat162*)&hi);
    __nv_bfloat162 l = __float22bfloat162_rn(make_float2(a - f.x, b - f.y));
    return *(uint32_t*)&l;
}
__device__ __forceinline__ void cp16(uint32_t smem, const void* g) {
    asm volatile("cp.async.cg.shared.global [%0], [%1], 16;"
                 :: "r"(smem), "l"(g) : "memory");
}
__device__ __forceinline__ void cp_commit() {
    asm volatile("cp.async.commit_group;" ::: "memory");
}
template <int N>
__device__ __forceinline__ void cp_wait() {
    asm volatile("cp.async.wait_group %0;" :: "n"(N) : "memory");
}

/* ---------------- weight reconstruction -> bf16 hi/lo -------------------- */
__global__ void build_weights(const float* __restrict__ cpq,
                              const float* __restrict__ cpk,
                              const float* __restrict__ cpv,
                              const float* __restrict__ cpo,
                              int ncp) {
    int i = blockIdx.x * 256 + threadIdx.x;
    if (i >= NW) return;
    const float dT = 1.0f / (float)(NW - 1);
    const float dX = 1.0f / (float)(ncp - 1);
    float t = (float)i * dT;
    int j = (int)((double)t * (double)(ncp - 1));
    if (j > ncp - 2) j = ncp - 2;
    if (j < 0) j = 0;
    while (j < ncp - 2 && (float)(j + 1) * dX <= t) j++;
    while (j > 0 && (float)j * dX > t) j--;
    float x0 = (float)j * dX;
    float x1 = (float)(j + 1) * dX;
    float f  = (t - x0) / (x1 - x0);
    const float* cps[4] = {cpq, cpk, cpv, cpo};
#pragma unroll
    for (int w = 0; w < 4; w++) {
        float a = cps[w][j];
        float val = fmaf(cps[w][j + 1] - a, f, a);
        __nv_bfloat16 hb = __float2bfloat16_rn(val);
        g_Wh[w][i] = hb;
        g_Wl[w][i] = __float2bfloat16_rn(val - __bfloat162float(hb));
    }
}

/* ---------------- split hidden_states -> bf16 hi/lo ---------------------- */
__global__ void split_x(const float* __restrict__ x) {
    int i = blockIdx.x * 256 + threadIdx.x;
    if (i >= MROWS * HID / 4) return;
    float4 v = *(const float4*)(x + 4 * (size_t)i);
    uint2 hi, lo; split4(v, hi, lo);
    *(uint2*)(g_Xh + 4 * (size_t)i) = hi;
    *(uint2*)(g_Xl + 4 * (size_t)i) = lo;
}

/* =============== bf16x3 HMMA GEMM, CTA 128x256, warp 64x32 =============== */
#define KC      32
#define NCHUNK  (KDIM / KC)
#define SA      40                      /* halfwords per smem row (80 B)    */
#define OFF_AH  0
#define OFF_AL  (128 * SA)
#define OFF_BH  (2 * 128 * SA)
#define OFF_BL  (OFF_BH + 256 * SA)
#define STG_HW  (OFF_BL + 256 * SA)     /* 30720 halfwords                  */
#define STG_B   (STG_HW * 2)            /* 61440 B                          */
#define GEMM_SMEM (2 * STG_B)           /* 122880 B                         */

__global__ void __launch_bounds__(512, 1) gemm_hmma(const __nv_bfloat16* __restrict__ Ah,
                                                    const __nv_bfloat16* __restrict__ Al,
                                                    const __nv_bfloat16* __restrict__ Bh,
                                                    const __nv_bfloat16* __restrict__ Bl,
                                                    float* __restrict__ C) {
    extern __shared__ char shg[];
    const uint32_t sb = smem_u32(shg);
    const int tid = threadIdx.x;
    const int lane = tid & 31, wid = tid >> 5;
    const int warp_m = wid >> 3;              /* 0..1  : 64-row block       */
    const int warp_n = wid & 7;               /* 0..7  : 32-col block       */
    const int m0 = blockIdx.y * 128, n0 = blockIdx.x * 256;

    /* cp.async coords */
    const int rA = tid >> 2;                  /* 0..127                     */
    const int cA = (tid & 3) << 3;            /* bf16 col 0,8,16,24         */
    const __nv_bfloat16* gAh = Ah + (size_t)(m0 + rA) * KDIM + cA;
    const __nv_bfloat16* gAl = Al + (size_t)(m0 + rA) * KDIM + cA;
    const int rB0 = tid >> 1 >> 1;            /* = tid>>2, rows 0..127      */
    const __nv_bfloat16* gBh0 = Bh + (size_t)(n0 + rB0) * KDIM + cA;
    const __nv_bfloat16* gBl0 = Bl + (size_t)(n0 + rB0) * KDIM + cA;
    const __nv_bfloat16* gBh1 = gBh0 + (size_t)128 * KDIM;
    const __nv_bfloat16* gBl1 = gBl0 + (size_t)128 * KDIM;
    const uint32_t dA  = sb + (uint32_t)(rA * SA + cA) * 2;
    const uint32_t dB0 = sb + (uint32_t)(rB0 * SA + cA) * 2;
    const uint32_t dB1 = dB0 + (uint32_t)(128 * SA) * 2;

    float acc[4][4][4];
#pragma unroll
    for (int i = 0; i < 4; i++)
#pragma unroll
        for (int j = 0; j < 4; j++)
#pragma unroll
            for (int q = 0; q < 4; q++) acc[i][j][q] = 0.0f;

    const int rowA = lane & 15, colA8 = (lane >= 16) ? 8 : 0;
    const int rowB = (lane & 7) + ((lane >= 16) ? 8 : 0);
    const int colB8 = (lane & 8) ? 8 : 0;
    const uint32_t aoff = (uint32_t)((warp_m * 64 + rowA) * SA + colA8) * 2;
    const uint32_t boff = (uint32_t)((warp_n * 32 + rowB) * SA + colB8) * 2;

    /* prologue: issue chunk 0 into stage 0 */
    {
        cp16(dA + OFF_AH * 2, gAh);
        cp16(dA + OFF_AL * 2, gAl);
        cp16(dB0 + OFF_BH * 2, gBh0);  cp16(dB1 + OFF_BH * 2, gBh1);
        cp16(dB0 + OFF_BL * 2, gBl0);  cp16(dB1 + OFF_BL * 2, gBl1);
        cp_commit();
    }

    for (int c = 0; c < NCHUNK; c++) {
        cp_wait<0>();
        __syncthreads();
        /* issue chunk c+1 into the other stage (overlaps compute below) */
        if (c + 1 < NCHUNK) {
            const uint32_t st = ((c + 1) & 1) * STG_B;
            const int kc = (c + 1) * KC;
            cp16(dA + st + OFF_AH * 2, gAh + kc);
            cp16(dA + st + OFF_AL * 2, gAl + kc);
            cp16(dB0 + st + OFF_BH * 2, gBh0 + kc);
            cp16(dB1 + st + OFF_BH * 2, gBh1 + kc);
            cp16(dB0 + st + OFF_BL * 2, gBl0 + kc);
            cp16(dB1 + st + OFF_BL * 2, gBl1 + kc);
            cp_commit();
        }

        const uint32_t stg = sb + (c & 1) * STG_B;
        const uint32_t tAh = stg + OFF_AH * 2, tAl = stg + OFF_AL * 2;
        const uint32_t tBh = stg + OFF_BH * 2, tBl = stg + OFF_BL * 2;
#pragma unroll
        for (int ks = 0; ks < 2; ks++) {
            const uint32_t ksoff = (uint32_t)(ks * 16) * 2;
            uint32_t ah[4][4], al[4][4];
#pragma unroll
            for (int mt = 0; mt < 4; mt++) {
                ldm_x4(ah[mt], tAh + aoff + ksoff + (uint32_t)(mt * 16 * SA) * 2);
                ldm_x4(al[mt], tAl + aoff + ksoff + (uint32_t)(mt * 16 * SA) * 2);
            }
#pragma unroll
            for (int g = 0; g < 2; g++) {
                uint32_t bh[4], bl[4];
                ldm_x4(bh, tBh + boff + ksoff + (uint32_t)(g * 16 * SA) * 2);
                ldm_x4(bl, tBl + boff + ksoff + (uint32_t)(g * 16 * SA) * 2);
#pragma unroll
                for (int mt = 0; mt < 4; mt++) {
                    float* a0 = acc[mt][2 * g];
                    float* a1 = acc[mt][2 * g + 1];
                    mma_bf16(a0, ah[mt], bh[0], bh[1]);
                    mma_bf16(a0, ah[mt], bl[0], bl[1]);
                    mma_bf16(a0, al[mt], bh[0], bh[1]);
                    mma_bf16(a1, ah[mt], bh[2], bh[3]);
                    mma_bf16(a1, ah[mt], bl[2], bl[3]);
                    mma_bf16(a1, al[mt], bh[2], bh[3]);
                }
            }
        }
    }

    const int rowg = lane >> 2, colg = (lane & 3) * 2;
#pragma unroll
    for (int mt = 0; mt < 4; mt++) {
#pragma unroll
        for (int nt = 0; nt < 4; nt++) {
            int r = m0 + warp_m * 64 + mt * 16 + rowg;
            int cc = n0 + warp_n * 32 + nt * 8 + colg;
            *(float2*)(C + (size_t)r * KDIM + cc) =
                make_float2(acc[mt][nt][0], acc[mt][nt][1]);
            *(float2*)(C + (size_t)(r + 8) * KDIM + cc) =
                make_float2(acc[mt][nt][2], acc[mt][nt][3]);
        }
    }
}

/* ========== bf16x3 HMMA causal flash attention =========================== */
#define FKS 136
#define FVS 72
#define OFF_QH 0
#define OFF_QL (128 * FKS)
#define OFF_KH (2 * 128 * FKS)
#define OFF_KL (OFF_KH + 64 * FKS)
#define OFF_VH (OFF_KL + 64 * FKS)
#define OFF_VL (OFF_VH + 128 * FVS)
#define FL_SMEM ((OFF_VL + 128 * FVS) * 2)

__global__ void __launch_bounds__(256, 1) flash_hmma(const float* __restrict__ Q,
                                                     const float* __restrict__ Km,
                                                     const float* __restrict__ Vm) {
    extern __shared__ char shf[];
    __nv_bfloat16* s = (__nv_bfloat16*)shf;
    const uint32_t sb = smem_u32(shf);
    const int tid = threadIdx.x, lane = tid & 31, wid = tid >> 5;
    const int qb = blockIdx.x, h = blockIdx.y, b = blockIdx.z;
    const int q0 = qb * 128;
    const int wm0 = wid * 16;
    const float scale = 0.08838834764831845f;

    const float* Qg = Q + (size_t)(b * SQ + q0) * HID + h * HD;
#pragma unroll
    for (int it = 0; it < 16; it++) {
        int idx = tid + it * 256;
        int r = idx >> 5, c4 = (idx & 31) << 2;
        float4 v = *(const float4*)(Qg + (size_t)r * HID + c4);
        uint2 hi, lo; split4(v, hi, lo);
        *(uint2*)(s + OFF_QH + r * FKS + c4) = hi;
        *(uint2*)(s + OFF_QL + r * FKS + c4) = lo;
    }

    const uint32_t aBaseH = sb + 2u * (OFF_QH + (wm0 + (lane & 15)) * FKS + ((lane >> 4) << 3));
    const uint32_t aBaseL = sb + 2u * (OFF_QL + (wm0 + (lane & 15)) * FKS + ((lane >> 4) << 3));
    const int krow = (lane & 7) + ((lane >> 4) << 3);
    const uint32_t kBaseH = sb + 2u * (OFF_KH + krow * FKS + (lane & 8));
    const uint32_t kBaseL = sb + 2u * (OFF_KL + krow * FKS + (lane & 8));
    const uint32_t vBaseH = sb + 2u * (OFF_VH + krow * FVS + (lane & 8));
    const uint32_t vBaseL = sb + 2u * (OFF_VL + krow * FVS + (lane & 8));

    float acc_o[16][4];
#pragma unroll
    for (int i = 0; i < 16; i++)
#pragma unroll
        for (int j = 0; j < 4; j++) acc_o[i][j] = 0.0f;
    float m0r = -1e30f, m1r = -1e30f, l0r = 0.0f, l1r = 0.0f;

    const int kb_max = 2 * qb + 1;
    const int r0g = q0 + wm0 + (lane >> 2);
    const int r1g = r0g + 8;

    for (int kb = 0; kb <= kb_max; kb++) {
        const int k0 = kb * 64;
        __syncthreads();
        const float* Kg = Km + (size_t)(b * SQ + k0) * HID + h * HD;
#pragma unroll
        for (int it = 0; it < 8; it++) {
            int idx = tid + it * 256;
            int r = idx >> 5, c4 = (idx & 31) << 2;
            float4 v = *(const float4*)(Kg + (size_t)r * HID + c4);
            uint2 hi, lo; split4(v, hi, lo);
            *(uint2*)(s + OFF_KH + r * FKS + c4) = hi;
            *(uint2*)(s + OFF_KL + r * FKS + c4) = lo;
        }
        const float* Vg = Vm + (size_t)(b * SQ + k0) * HID + h * HD;
#pragma unroll
        for (int it = 0; it < 8; it++) {
            int idx = tid + it * 256;
            int r = idx & 63, c4 = (idx >> 6) << 2;
            float4 v = *(const float4*)(Vg + (size_t)r * HID + c4);
            float e[4] = {v.x, v.y, v.z, v.w};
#pragma unroll
            for (int q = 0; q < 4; q++) {
                __nv_bfloat16 hb = __float2bfloat16_rn(e[q]);
                __nv_bfloat16 lb = __float2bfloat16_rn(e[q] - __bfloat162float(hb));
                s[OFF_VH + (c4 + q) * FVS + r] = hb;
                s[OFF_VL + (c4 + q) * FVS + r] = lb;
            }
        }
        __syncthreads();

        if (k0 > q0 + wm0) continue;

        float accs[8][4];
#pragma unroll
        for (int i = 0; i < 8; i++)
#pragma unroll
            for (int j = 0; j < 4; j++) accs[i][j] = 0.0f;
#pragma unroll
        for (int ks = 0; ks < 8; ks++) {
            uint32_t ah[4], al[4];
            ldm_x4(ah, aBaseH + ks * 32);
            ldm_x4(al, aBaseL + ks * 32);
#pragma unroll
            for (int ng = 0; ng < 4; ng++) {
                uint32_t bh[4], bl[4];
                ldm_x4(bh, kBaseH + (uint32_t)(ng * 16 * FKS) * 2 + ks * 32);
                ldm_x4(bl, kBaseL + (uint32_t)(ng * 16 * FKS) * 2 + ks * 32);
                mma_bf16(accs[2 * ng],     ah, bh[0], bh[1]);
                mma_bf16(accs[2 * ng],     ah, bl[0], bl[1]);
                mma_bf16(accs[2 * ng],     al, bh[0], bh[1]);
                mma_bf16(accs[2 * ng + 1], ah, bh[2], bh[3]);
                mma_bf16(accs[2 * ng + 1], ah, bl[2], bl[3]);
                mma_bf16(accs[2 * ng + 1], al, bh[2], bh[3]);
            }
        }

#pragma unroll
        for (int nt = 0; nt < 8; nt++) {
            int cb = k0 + nt * 8 + (lane & 3) * 2;
            accs[nt][0] = accs[nt][0] * scale + ((cb     > r0g) ? -1e9f : 0.0f);
            accs[nt][1] = accs[nt][1] * scale + ((cb + 1 > r0g) ? -1e9f : 0.0f);
            accs[nt][2] = accs[nt][2] * scale + ((cb     > r1g) ? -1e9f : 0.0f);
            accs[nt][3] = accs[nt][3] * scale + ((cb + 1 > r1g) ? -1e9f : 0.0f);
        }

        float mx0 = -1e30f, mx1 = -1e30f;
#pragma unroll
        for (int nt = 0; nt < 8; nt++) {
            mx0 = fmaxf(mx0, fmaxf(accs[nt][0], accs[nt][1]));
            mx1 = fmaxf(mx1, fmaxf(accs[nt][2], accs[nt][3]));
        }
        mx0 = fmaxf(mx0, __shfl_xor_sync(0xffffffffu, mx0, 1));
        mx0 = fmaxf(mx0, __shfl_xor_sync(0xffffffffu, mx0, 2));
        mx1 = fmaxf(mx1, __shfl_xor_sync(0xffffffffu, mx1, 1));
        mx1 = fmaxf(mx1, __shfl_xor_sync(0xffffffffu, mx1, 2));
        float mn0 = fmaxf(m0r, mx0), mn1 = fmaxf(m1r, mx1);
        float al0 = __expf(m0r - mn0), al1 = __expf(m1r - mn1);
        m0r = mn0; m1r = mn1;
        float rs0 = 0.0f, rs1 = 0.0f;
#pragma unroll
        for (int nt = 0; nt < 8; nt++) {
            accs[nt][0] = __expf(accs[nt][0] - mn0);
            accs[nt][1] = __expf(accs[nt][1] - mn0);
            accs[nt][2] = __expf(accs[nt][2] - mn1);
            accs[nt][3] = __expf(accs[nt][3] - mn1);
            rs0 += accs[nt][0] + accs[nt][1];
            rs1 += accs[nt][2] + accs[nt][3];
        }
        rs0 += __shfl_xor_sync(0xffffffffu, rs0, 1);
        rs0 += __shfl_xor_sync(0xffffffffu, rs0, 2);
        rs1 += __shfl_xor_sync(0xffffffffu, rs1, 1);
        rs1 += __shfl_xor_sync(0xffffffffu, rs1, 2);
        l0r = l0r * al0 + rs0;
        l1r = l1r * al1 + rs1;
#pragma unroll
        for (int i = 0; i < 16; i++) {
            acc_o[i][0] *= al0; acc_o[i][1] *= al0;
            acc_o[i][2] *= al1; acc_o[i][3] *= al1;
        }

        uint32_t ph[4][4], pl[4][4];
#pragma unroll
        for (int kk = 0; kk < 4; kk++) {
            int n0t = 2 * kk, n1t = 2 * kk + 1;
            ph[kk][0] = pack_hi(accs[n0t][0], accs[n0t][1]);
            pl[kk][0] = pack_lo(accs[n0t][0], accs[n0t][1], ph[kk][0]);
            ph[kk][1] = pack_hi(accs[n0t][2], accs[n0t][3]);
            pl[kk][1] = pack_lo(accs[n0t][2], accs[n0t][3], ph[kk][1]);
            ph[kk][2] = pack_hi(accs[n1t][0], accs[n1t][1]);
            pl[kk][2] = pack_lo(accs[n1t][0], accs[n1t][1], ph[kk][2]);
            ph[kk][3] = pack_hi(accs[n1t][2], accs[n1t][3]);
            pl[kk][3] = pack_lo(accs[n1t][2], accs[n1t][3], ph[kk][3]);
        }

#pragma unroll
        for (int kk = 0; kk < 4; kk++) {
#pragma unroll
            for (int g = 0; g < 8; g++) {
                uint32_t vh[4], vl[4];
                ldm_x4(vh, vBaseH + (uint32_t)(g * 16 * FVS) * 2 + kk * 32);
                ldm_x4(vl, vBaseL + (uint32_t)(g * 16 * FVS) * 2 + kk * 32);
                mma_bf16(acc_o[2 * g],     ph[kk], vh[0], vh[1]);
                mma_bf16(acc_o[2 * g],     ph[kk], vl[0], vl[1]);
                mma_bf16(acc_o[2 * g],     pl[kk], vh[0], vh[1]);
                mma_bf16(acc_o[2 * g + 1], ph[kk], vh[2], vh[3]);
                mma_bf16(acc_o[2 * g + 1], ph[kk], vl[2], vl[3]);
                mma_bf16(acc_o[2 * g + 1], pl[kk], vh[2], vh[3]);
            }
        }
    }

    float inv0 = 1.0f / l0r, inv1 = 1.0f / l1r;
    size_t base0 = (size_t)(b * SQ + r0g) * HID + h * HD;
    size_t base1 = base0 + (size_t)8 * HID;
#pragma unroll
    for (int nto = 0; nto < 16; nto++) {
        int c = nto * 8 + (lane & 3) * 2;
        float v0 = acc_o[nto][0] * inv0, v1 = acc_o[nto][1] * inv0;
        uint32_t hw = pack_hi(v0, v1);
        *(uint32_t*)(g_Ah + base0 + c) = hw;
        *(uint32_t*)(g_Al + base0 + c) = pack_lo(v0, v1, hw);
        float v2 = acc_o[nto][2] * inv1, v3 = acc_o[nto][3] * inv1;
        hw = pack_hi(v2, v3);
        *(uint32_t*)(g_Ah + base1 + c) = hw;
        *(uint32_t*)(g_Al + base1 + c) = pack_lo(v2, v3, hw);
    }
}

/* ---------------- launcher ---------------------------------------------- */
extern "C" void kernel_launch(void* const* d_in, const int* in_sizes, int n_in,
                              void* d_out, int out_size) {
    (void)n_in; (void)out_size;
    const float* x   = (const float*)d_in[0];
    const float* cpq = (const float*)d_in[1];
    const float* cpk = (const float*)d_in[2];
    const float* cpv = (const float*)d_in[3];
    const float* cpo = (const float*)d_in[4];
    float* out = (float*)d_out;
    int ncp = in_sizes[1];

    __nv_bfloat16 *pWh, *pWl, *pXh, *pXl, *pAh, *pAl;
    float *pQ, *pK, *pV;
    cudaGetSymbolAddress((void**)&pWh, g_Wh);
    cudaGetSymbolAddress((void**)&pWl, g_Wl);
    cudaGetSymbolAddress((void**)&pXh, g_Xh);
    cudaGetSymbolAddress((void**)&pXl, g_Xl);
    cudaGetSymbolAddress((void**)&pAh, g_Ah);
    cudaGetSymbolAddress((void**)&pAl, g_Al);
    cudaGetSymbolAddress((void**)&pQ, g_Q);
    cudaGetSymbolAddress((void**)&pK, g_K);
    cudaGetSymbolAddress((void**)&pV, g_V);

    build_weights<<<(NW + 255) / 256, 256>>>(cpq, cpk, cpv, cpo, ncp);
    split_x<<<(MROWS * HID / 4 + 255) / 256, 256>>>(x);

    cudaFuncSetAttribute(gemm_hmma, cudaFuncAttributeMaxDynamicSharedMemorySize,
                         GEMM_SMEM);
    dim3 gg(HID / 256, MROWS / 128);
    gemm_hmma<<<gg, 512, GEMM_SMEM>>>(pXh, pXl, pWh + 0 * (size_t)NW, pWl + 0 * (size_t)NW, pQ);
    gemm_hmma<<<gg, 512, GEMM_SMEM>>>(pXh, pXl, pWh + 1 * (size_t)NW, pWl + 1 * (size_t)NW, pK);
    gemm_hmma<<<gg, 512, GEMM_SMEM>>>(pXh, pXl, pWh + 2 * (size_t)NW, pWl + 2 * (size_t)NW, pV);

    cudaFuncSetAttribute(flash_hmma, cudaFuncAttributeMaxDynamicSharedMemorySize,
                         FL_SMEM);
    flash_hmma<<<dim3(SQ / 128, NHEAD, NB), 256, FL_SMEM>>>(pQ, pK, pV);

    gemm_hmma<<<gg, 512, GEMM_SMEM>>>(pAh, pAl, pWh + 3 * (size_t)NW, pWl + 3 * (size_t)NW, out);
}

// round 8
// speedup vs baseline: 1.0289x; 1.0009x over previous
#include <cuda_runtime.h>
#include <cuda_bf16.h>
#include <math.h>
#include <stdint.h>

#define HID   2048
#define NB    2
#define SQ    2048
#define NHEAD 16
#define HD    128
#define MROWS (NB * SQ)        /* 4096 */
#define NW    (HID * HID)      /* 4194304 */
#define KDIM  2048

/* ---------------- scratch (device globals; no allocation allowed) -------- */
__device__ __nv_bfloat16 g_Wh[4][NW];
__device__ __nv_bfloat16 g_Wl[4][NW];
__device__ __nv_bfloat16 g_Xh[MROWS * HID];
__device__ __nv_bfloat16 g_Xl[MROWS * HID];
__device__ __nv_bfloat16 g_Ah[MROWS * HID];
__device__ __nv_bfloat16 g_Al[MROWS * HID];
__device__ float g_Q[MROWS * HID];
__device__ float g_K[MROWS * HID];
__device__ float g_V[MROWS * HID];

__device__ __forceinline__ uint32_t smem_u32(const void* p) {
    uint32_t a;
    asm("{ .reg .u64 t; cvta.to.shared.u64 t, %1; cvt.u32.u64 %0, t; }"
        : "=r"(a) : "l"(p));
    return a;
}
__device__ __forceinline__ void ldm_x4(uint32_t* r, uint32_t addr) {
    asm volatile("ldmatrix.sync.aligned.m8n8.x4.shared.b16 {%0,%1,%2,%3}, [%4];"
                 : "=r"(r[0]), "=r"(r[1]), "=r"(r[2]), "=r"(r[3]) : "r"(addr));
}
__device__ __forceinline__ void mma_bf16(float* d, const uint32_t* a,
                                         uint32_t b0, uint32_t b1) {
    asm volatile("mma.sync.aligned.m16n8k16.row.col.f32.bf16.bf16.f32 "
                 "{%0,%1,%2,%3},{%4,%5,%6,%7},{%8,%9},{%0,%1,%2,%3};"
                 : "+f"(d[0]), "+f"(d[1]), "+f"(d[2]), "+f"(d[3])
                 : "r"(a[0]), "r"(a[1]), "r"(a[2]), "r"(a[3]), "r"(b0), "r"(b1));
}
__device__ __forceinline__ void split4(float4 v, uint2& hi, uint2& lo) {
    __nv_bfloat162 h0 = __float22bfloat162_rn(make_float2(v.x, v.y));
    __nv_bfloat162 h1 = __float22bfloat162_rn(make_float2(v.z, v.w));
    float2 f0 = __bfloat1622float2(h0), f1 = __bfloat1622float2(h1);
    __nv_bfloat162 l0 = __float22bfloat162_rn(make_float2(v.x - f0.x, v.y - f0.y));
    __nv_bfloat162 l1 = __float22bfloat162_rn(make_float2(v.z - f1.x, v.w - f1.y));
    hi = make_uint2(*(uint32_t*)&h0, *(uint32_t*)&h1);
    lo = make_uint2(*(uint32_t*)&l0, *(uint32_t*)&l1);
}
__device__ __forceinline__ uint32_t pack_hi(float a, float b) {
    __nv_bfloat162 h = __float22bfloat162_rn(make_float2(a, b));
    return *(uint32_t*)&h;
}
__device__ __forceinline__ uint32_t pack_lo(float a, float b, uint32_t hi) {
    float2 f = __bfloat1622float2(*(__nv_bfloat162*)&hi);
    __nv_bfloat162 l = __float22bfloat162_rn(make_float2(a - f.x, b - f.y));
    return *(uint32_t*)&l;
}
__device__ __forceinline__ void cp16(uint32_t smem, const void* g) {
    asm volatile("cp.async.cg.shared.global [%0], [%1], 16;"
                 :: "r"(smem), "l"(g) : "memory");
}
__device__ __forceinline__ void cp_commit() {
    asm volatile("cp.async.commit_group;" ::: "memory");
}
template <int N>
__device__ __forceinline__ void cp_wait() {
    asm volatile("cp.async.wait_group %0;" :: "n"(N) : "memory");
}

/* ---------------- weight reconstruction -> bf16 hi/lo -------------------- */
__global__ void build_weights(const float* __restrict__ cpq,
                              const float* __restrict__ cpk,
                              const float* __restrict__ cpv,
                              const float* __restrict__ cpo,
                              int ncp) {
    int i = blockIdx.x * 256 + threadIdx.x;
    if (i >= NW) return;
    const float dT = 1.0f / (float)(NW - 1);
    const float dX = 1.0f / (float)(ncp - 1);
    float t = (float)i * dT;
    int j = (int)((double)t * (double)(ncp - 1));
    if (j > ncp - 2) j = ncp - 2;
    if (j < 0) j = 0;
    while (j < ncp - 2 && (float)(j + 1) * dX <= t) j++;
    while (j > 0 && (float)j * dX > t) j--;
    float x0 = (float)j * dX;
    float x1 = (float)(j + 1) * dX;
    float f  = (t - x0) / (x1 - x0);
    const float* cps[4] = {cpq, cpk, cpv, cpo};
#pragma unroll
    for (int w = 0; w < 4; w++) {
        float a = cps[w][j];
        float val = fmaf(cps[w][j + 1] - a, f, a);
        __nv_bfloat16 hb = __float2bfloat16_rn(val);
        g_Wh[w][i] = hb;
        g_Wl[w][i] = __float2bfloat16_rn(val - __bfloat162float(hb));
    }
}

/* ---------------- split hidden_states -> bf16 hi/lo ---------------------- */
__global__ void split_x(const float* __restrict__ x) {
    int i = blockIdx.x * 256 + threadIdx.x;
    if (i >= MROWS * HID / 4) return;
    float4 v = *(const float4*)(x + 4 * (size_t)i);
    uint2 hi, lo; split4(v, hi, lo);
    *(uint2*)(g_Xh + 4 * (size_t)i) = hi;
    *(uint2*)(g_Xl + 4 * (size_t)i) = lo;
}

/* =============== bf16x3 HMMA GEMM, CTA 128x256, warp 64x32 =============== */
#define KC      32
#define NCHUNK  (KDIM / KC)
#define SA      40
#define OFF_AH  0
#define OFF_AL  (128 * SA)
#define OFF_BH  (2 * 128 * SA)
#define OFF_BL  (OFF_BH + 256 * SA)
#define STG_HW  (OFF_BL + 256 * SA)
#define STG_B   (STG_HW * 2)
#define GEMM_SMEM (2 * STG_B)

__global__ void __launch_bounds__(512, 1) gemm_hmma(const __nv_bfloat16* __restrict__ Ah,
                                                    const __nv_bfloat16* __restrict__ Al,
                                                    const __nv_bfloat16* __restrict__ Bh,
                                                    const __nv_bfloat16* __restrict__ Bl,
                                                    float* __restrict__ C) {
    extern __shared__ char shg[];
    const uint32_t sb = smem_u32(shg);
    const int tid = threadIdx.x;
    const int lane = tid & 31, wid = tid >> 5;
    const int warp_m = wid >> 3;
    const int warp_n = wid & 7;
    const int m0 = blockIdx.y * 128, n0 = blockIdx.x * 256;

    const int rA = tid >> 2;
    const int cA = (tid & 3) << 3;
    const __nv_bfloat16* gAh = Ah + (size_t)(m0 + rA) * KDIM + cA;
    const __nv_bfloat16* gAl = Al + (size_t)(m0 + rA) * KDIM + cA;
    const __nv_bfloat16* gBh0 = Bh + (size_t)(n0 + rA) * KDIM + cA;
    const __nv_bfloat16* gBl0 = Bl + (size_t)(n0 + rA) * KDIM + cA;
    const __nv_bfloat16* gBh1 = gBh0 + (size_t)128 * KDIM;
    const __nv_bfloat16* gBl1 = gBl0 + (size_t)128 * KDIM;
    const uint32_t dA  = sb + (uint32_t)(rA * SA + cA) * 2;
    const uint32_t dB0 = dA;
    const uint32_t dB1 = dB0 + (uint32_t)(128 * SA) * 2;

    float acc[4][4][4];
#pragma unroll
    for (int i = 0; i < 4; i++)
#pragma unroll
        for (int j = 0; j < 4; j++)
#pragma unroll
            for (int q = 0; q < 4; q++) acc[i][j][q] = 0.0f;

    const int rowA = lane & 15, colA8 = (lane >= 16) ? 8 : 0;
    const int rowB = (lane & 7) + ((lane >= 16) ? 8 : 0);
    const int colB8 = (lane & 8) ? 8 : 0;
    const uint32_t aoff = (uint32_t)((warp_m * 64 + rowA) * SA + colA8) * 2;
    const uint32_t boff = (uint32_t)((warp_n * 32 + rowB) * SA + colB8) * 2;

    {
        cp16(dA + OFF_AH * 2, gAh);
        cp16(dA + OFF_AL * 2, gAl);
        cp16(dB0 + OFF_BH * 2, gBh0);  cp16(dB1 + OFF_BH * 2, gBh1);
        cp16(dB0 + OFF_BL * 2, gBl0);  cp16(dB1 + OFF_BL * 2, gBl1);
        cp_commit();
    }

    for (int c = 0; c < NCHUNK; c++) {
        cp_wait<0>();
        __syncthreads();
        if (c + 1 < NCHUNK) {
            const uint32_t st = ((c + 1) & 1) * STG_B;
            const int kc = (c + 1) * KC;
            cp16(dA + st + OFF_AH * 2, gAh + kc);
            cp16(dA + st + OFF_AL * 2, gAl + kc);
            cp16(dB0 + st + OFF_BH * 2, gBh0 + kc);
            cp16(dB1 + st + OFF_BH * 2, gBh1 + kc);
            cp16(dB0 + st + OFF_BL * 2, gBl0 + kc);
            cp16(dB1 + st + OFF_BL * 2, gBl1 + kc);
            cp_commit();
        }

        const uint32_t stg = sb + (c & 1) * STG_B;
        const uint32_t tAh = stg + OFF_AH * 2, tAl = stg + OFF_AL * 2;
        const uint32_t tBh = stg + OFF_BH * 2, tBl = stg + OFF_BL * 2;
#pragma unroll
        for (int ks = 0; ks < 2; ks++) {
            const uint32_t ksoff = (uint32_t)(ks * 16) * 2;
            uint32_t ah[4][4], al[4][4];
#pragma unroll
            for (int mt = 0; mt < 4; mt++) {
                ldm_x4(ah[mt], tAh + aoff + ksoff + (uint32_t)(mt * 16 * SA) * 2);
                ldm_x4(al[mt], tAl + aoff + ksoff + (uint32_t)(mt * 16 * SA) * 2);
            }
#pragma unroll
            for (int g = 0; g < 2; g++) {
                uint32_t bh[4], bl[4];
                ldm_x4(bh, tBh + boff + ksoff + (uint32_t)(g * 16 * SA) * 2);
                ldm_x4(bl, tBl + boff + ksoff + (uint32_t)(g * 16 * SA) * 2);
                /* term-major: 8 independent MMAs between same-acc reuse */
#pragma unroll
                for (int mt = 0; mt < 4; mt++) {
                    mma_bf16(acc[mt][2 * g],     ah[mt], bh[0], bh[1]);
                    mma_bf16(acc[mt][2 * g + 1], ah[mt], bh[2], bh[3]);
                }
#pragma unroll
                for (int mt = 0; mt < 4; mt++) {
                    mma_bf16(acc[mt][2 * g],     ah[mt], bl[0], bl[1]);
                    mma_bf16(acc[mt][2 * g + 1], ah[mt], bl[2], bl[3]);
                }
#pragma unroll
                for (int mt = 0; mt < 4; mt++) {
                    mma_bf16(acc[mt][2 * g],     al[mt], bh[0], bh[1]);
                    mma_bf16(acc[mt][2 * g + 1], al[mt], bh[2], bh[3]);
                }
            }
        }
    }

    const int rowg = lane >> 2, colg = (lane & 3) * 2;
#pragma unroll
    for (int mt = 0; mt < 4; mt++) {
#pragma unroll
        for (int nt = 0; nt < 4; nt++) {
            int r = m0 + warp_m * 64 + mt * 16 + rowg;
            int cc = n0 + warp_n * 32 + nt * 8 + colg;
            *(float2*)(C + (size_t)r * KDIM + cc) =
                make_float2(acc[mt][nt][0], acc[mt][nt][1]);
            *(float2*)(C + (size_t)(r + 8) * KDIM + cc) =
                make_float2(acc[mt][nt][2], acc[mt][nt][3]);
        }
    }
}

/* ========== bf16x3 HMMA causal flash attention =========================== */
#define FKS 136
#define FVS 72
#define OFF_QH 0
#define OFF_QL (128 * FKS)
#define OFF_KH (2 * 128 * FKS)
#define OFF_KL (OFF_KH + 64 * FKS)
#define OFF_VH (OFF_KL + 64 * FKS)
#define OFF_VL (OFF_VH + 128 * FVS)
#define FL_SMEM ((OFF_VL + 128 * FVS) * 2)

__global__ void __launch_bounds__(256, 1) flash_hmma(const float* __restrict__ Q,
                                                     const float* __restrict__ Km,
                                                     const float* __restrict__ Vm) {
    extern __shared__ char shf[];
    __nv_bfloat16* s = (__nv_bfloat16*)shf;
    const uint32_t sb = smem_u32(shf);
    const int tid = threadIdx.x, lane = tid & 31, wid = tid >> 5;
    const int qb = blockIdx.x, h = blockIdx.y, b = blockIdx.z;
    const int q0 = qb * 128;
    const int wm0 = wid * 16;
    const float scale = 0.08838834764831845f;

    const float* Qg = Q + (size_t)(b * SQ + q0) * HID + h * HD;
#pragma unroll
    for (int it = 0; it < 16; it++) {
        int idx = tid + it * 256;
        int r = idx >> 5, c4 = (idx & 31) << 2;
        float4 v = *(const float4*)(Qg + (size_t)r * HID + c4);
        uint2 hi, lo; split4(v, hi, lo);
        *(uint2*)(s + OFF_QH + r * FKS + c4) = hi;
        *(uint2*)(s + OFF_QL + r * FKS + c4) = lo;
    }

    const uint32_t aBaseH = sb + 2u * (OFF_QH + (wm0 + (lane & 15)) * FKS + ((lane >> 4) << 3));
    const uint32_t aBaseL = sb + 2u * (OFF_QL + (wm0 + (lane & 15)) * FKS + ((lane >> 4) << 3));
    const int krow = (lane & 7) + ((lane >> 4) << 3);
    const uint32_t kBaseH = sb + 2u * (OFF_KH + krow * FKS + (lane & 8));
    const uint32_t kBaseL = sb + 2u * (OFF_KL + krow * FKS + (lane & 8));
    const uint32_t vBaseH = sb + 2u * (OFF_VH + krow * FVS + (lane & 8));
    const uint32_t vBaseL = sb + 2u * (OFF_VL + krow * FVS + (lane & 8));

    float acc_o[16][4];
#pragma unroll
    for (int i = 0; i < 16; i++)
#pragma unroll
        for (int j = 0; j < 4; j++) acc_o[i][j] = 0.0f;
    float m0r = -1e30f, m1r = -1e30f, l0r = 0.0f, l1r = 0.0f;

    const int kb_max = 2 * qb + 1;
    const int r0g = q0 + wm0 + (lane >> 2);
    const int r1g = r0g + 8;

    for (int kb = 0; kb <= kb_max; kb++) {
        const int k0 = kb * 64;
        __syncthreads();
        const float* Kg = Km + (size_t)(b * SQ + k0) * HID + h * HD;
#pragma unroll
        for (int it = 0; it < 8; it++) {
            int idx = tid + it * 256;
            int r = idx >> 5, c4 = (idx & 31) << 2;
            float4 v = *(const float4*)(Kg + (size_t)r * HID + c4);
            uint2 hi, lo; split4(v, hi, lo);
            *(uint2*)(s + OFF_KH + r * FKS + c4) = hi;
            *(uint2*)(s + OFF_KL + r * FKS + c4) = lo;
        }
        const float* Vg = Vm + (size_t)(b * SQ + k0) * HID + h * HD;
#pragma unroll
        for (int it = 0; it < 8; it++) {
            int idx = tid + it * 256;
            int r = idx & 63, c4 = (idx >> 6) << 2;
            float4 v = *(const float4*)(Vg + (size_t)r * HID + c4);
            float e[4] = {v.x, v.y, v.z, v.w};
#pragma unroll
            for (int q = 0; q < 4; q++) {
                __nv_bfloat16 hb = __float2bfloat16_rn(e[q]);
                __nv_bfloat16 lb = __float2bfloat16_rn(e[q] - __bfloat162float(hb));
                s[OFF_VH + (c4 + q) * FVS + r] = hb;
                s[OFF_VL + (c4 + q) * FVS + r] = lb;
            }
        }
        __syncthreads();

        if (k0 > q0 + wm0) continue;

        float accs[8][4];
#pragma unroll
        for (int i = 0; i < 8; i++)
#pragma unroll
            for (int j = 0; j < 4; j++) accs[i][j] = 0.0f;
#pragma unroll
        for (int ks = 0; ks < 8; ks++) {
            uint32_t ah[4], al[4];
            ldm_x4(ah, aBaseH + ks * 32);
            ldm_x4(al, aBaseL + ks * 32);
            uint32_t bh[4][4], bl[4][4];
#pragma unroll
            for (int ng = 0; ng < 4; ng++) {
                ldm_x4(bh[ng], kBaseH + (uint32_t)(ng * 16 * FKS) * 2 + ks * 32);
                ldm_x4(bl[ng], kBaseL + (uint32_t)(ng * 16 * FKS) * 2 + ks * 32);
            }
            /* term-major: 8 independent MMAs between same-acc reuse */
#pragma unroll
            for (int ng = 0; ng < 4; ng++) {
                mma_bf16(accs[2 * ng],     ah, bh[ng][0], bh[ng][1]);
                mma_bf16(accs[2 * ng + 1], ah, bh[ng][2], bh[ng][3]);
            }
#pragma unroll
            for (int ng = 0; ng < 4; ng++) {
                mma_bf16(accs[2 * ng],     ah, bl[ng][0], bl[ng][1]);
                mma_bf16(accs[2 * ng + 1], ah, bl[ng][2], bl[ng][3]);
            }
#pragma unroll
            for (int ng = 0; ng < 4; ng++) {
                mma_bf16(accs[2 * ng],     al, bh[ng][0], bh[ng][1]);
                mma_bf16(accs[2 * ng + 1], al, bh[ng][2], bh[ng][3]);
            }
        }

#pragma unroll
        for (int nt = 0; nt < 8; nt++) {
            int cb = k0 + nt * 8 + (lane & 3) * 2;
            accs[nt][0] = accs[nt][0] * scale + ((cb     > r0g) ? -1e9f : 0.0f);
            accs[nt][1] = accs[nt][1] * scale + ((cb + 1 > r0g) ? -1e9f : 0.0f);
            accs[nt][2] = accs[nt][2] * scale + ((cb     > r1g) ? -1e9f : 0.0f);
            accs[nt][3] = accs[nt][3] * scale + ((cb + 1 > r1g) ? -1e9f : 0.0f);
        }

        float mx0 = -1e30f, mx1 = -1e30f;
#pragma unroll
        for (int nt = 0; nt < 8; nt++) {
            mx0 = fmaxf(mx0, fmaxf(accs[nt][0], accs[nt][1]));
            mx1 = fmaxf(mx1, fmaxf(accs[nt][2], accs[nt][3]));
        }
        mx0 = fmaxf(mx0, __shfl_xor_sync(0xffffffffu, mx0, 1));
        mx0 = fmaxf(mx0, __shfl_xor_sync(0xffffffffu, mx0, 2));
        mx1 = fmaxf(mx1, __shfl_xor_sync(0xffffffffu, mx1, 1));
        mx1 = fmaxf(mx1, __shfl_xor_sync(0xffffffffu, mx1, 2));
        float mn0 = fmaxf(m0r, mx0), mn1 = fmaxf(m1r, mx1);
        float al0 = __expf(m0r - mn0), al1 = __expf(m1r - mn1);
        m0r = mn0; m1r = mn1;
        float rs0 = 0.0f, rs1 = 0.0f;
#pragma unroll
        for (int nt = 0; nt < 8; nt++) {
            accs[nt][0] = __expf(accs[nt][0] - mn0);
            accs[nt][1] = __expf(accs[nt][1] - mn0);
            accs[nt][2] = __expf(accs[nt][2] - mn1);
            accs[nt][3] = __expf(accs[nt][3] - mn1);
            rs0 += accs[nt][0] + accs[nt][1];
            rs1 += accs[nt][2] + accs[nt][3];
        }
        rs0 += __shfl_xor_sync(0xffffffffu, rs0, 1);
        rs0 += __shfl_xor_sync(0xffffffffu, rs0, 2);
        rs1 += __shfl_xor_sync(0xffffffffu, rs1, 1);
        rs1 += __shfl_xor_sync(0xffffffffu, rs1, 2);
        l0r = l0r * al0 + rs0;
        l1r = l1r * al1 + rs1;
#pragma unroll
        for (int i = 0; i < 16; i++) {
            acc_o[i][0] *= al0; acc_o[i][1] *= al0;
            acc_o[i][2] *= al1; acc_o[i][3] *= al1;
        }

        uint32_t ph[4][4], pl[4][4];
#pragma unroll
        for (int kk = 0; kk < 4; kk++) {
            int n0t = 2 * kk, n1t = 2 * kk + 1;
            ph[kk][0] = pack_hi(accs[n0t][0], accs[n0t][1]);
            pl[kk][0] = pack_lo(accs[n0t][0], accs[n0t][1], ph[kk][0]);
            ph[kk][1] = pack_hi(accs[n0t][2], accs[n0t][3]);
            pl[kk][1] = pack_lo(accs[n0t][2], accs[n0t][3], ph[kk][1]);
            ph[kk][2] = pack_hi(accs[n1t][0], accs[n1t][1]);
            pl[kk][2] = pack_lo(accs[n1t][0], accs[n1t][1], ph[kk][2]);
            ph[kk][3] = pack_hi(accs[n1t][2], accs[n1t][3]);
            pl[kk][3] = pack_lo(accs[n1t][2], accs[n1t][3], ph[kk][3]);
        }

        /* O += P V, 4 V-groups at a time, term-major (distance 8) */
#pragma unroll
        for (int kk = 0; kk < 4; kk++) {
#pragma unroll
            for (int gb = 0; gb < 8; gb += 4) {
                uint32_t vh[4][4], vl[4][4];
#pragma unroll
                for (int g = 0; g < 4; g++) {
                    ldm_x4(vh[g], vBaseH + (uint32_t)((gb + g) * 16 * FVS) * 2 + kk * 32);
                    ldm_x4(vl[g], vBaseL + (uint32_t)((gb + g) * 16 * FVS) * 2 + kk * 32);
                }
#pragma unroll
                for (int g = 0; g < 4; g++) {
                    mma_bf16(acc_o[2 * (gb + g)],     ph[kk], vh[g][0], vh[g][1]);
                    mma_bf16(acc_o[2 * (gb + g) + 1], ph[kk], vh[g][2], vh[g][3]);
                }
#pragma unroll
                for (int g = 0; g < 4; g++) {
                    mma_bf16(acc_o[2 * (gb + g)],     ph[kk], vl[g][0], vl[g][1]);
                    mma_bf16(acc_o[2 * (gb + g) + 1], ph[kk], vl[g][2], vl[g][3]);
                }
#pragma unroll
                for (int g = 0; g < 4; g++) {
                    mma_bf16(acc_o[2 * (gb + g)],     pl[kk], vh[g][0], vh[g][1]);
                    mma_bf16(acc_o[2 * (gb + g) + 1], pl[kk], vh[g][2], vh[g][3]);
                }
            }
        }
    }

    float inv0 = 1.0f / l0r, inv1 = 1.0f / l1r;
    size_t base0 = (size_t)(b * SQ + r0g) * HID + h * HD;
    size_t base1 = base0 + (size_t)8 * HID;
#pragma unroll
    for (int nto = 0; nto < 16; nto++) {
        int c = nto * 8 + (lane & 3) * 2;
        float v0 = acc_o[nto][0] * inv0, v1 = acc_o[nto][1] * inv0;
        uint32_t hw = pack_hi(v0, v1);
        *(uint32_t*)(g_Ah + base0 + c) = hw;
        *(uint32_t*)(g_Al + base0 + c) = pack_lo(v0, v1, hw);
        float v2 = acc_o[nto][2] * inv1, v3 = acc_o[nto][3] * inv1;
        hw = pack_hi(v2, v3);
        *(uint32_t*)(g_Ah + base1 + c) = hw;
        *(uint32_t*)(g_Al + base1 + c) = pack_lo(v2, v3, hw);
    }
}

/* ---------------- launcher ---------------------------------------------- */
extern "C" void kernel_launch(void* const* d_in, const int* in_sizes, int n_in,
                              void* d_out, int out_size) {
    (void)n_in; (void)out_size;
    const float* x   = (const float*)d_in[0];
    const float* cpq = (const float*)d_in[1];
    const float* cpk = (const float*)d_in[2];
    const float* cpv = (const float*)d_in[3];
    const float* cpo = (const float*)d_in[4];
    float* out = (float*)d_out;
    int ncp = in_sizes[1];

    __nv_bfloat16 *pWh, *pWl, *pXh, *pXl, *pAh, *pAl;
    float *pQ, *pK, *pV;
    cudaGetSymbolAddress((void**)&pWh, g_Wh);
    cudaGetSymbolAddress((void**)&pWl, g_Wl);
    cudaGetSymbolAddress((void**)&pXh, g_Xh);
    cudaGetSymbolAddress((void**)&pXl, g_Xl);
    cudaGetSymbolAddress((void**)&pAh, g_Ah);
    cudaGetSymbolAddress((void**)&pAl, g_Al);
    cudaGetSymbolAddress((void**)&pQ, g_Q);
    cudaGetSymbolAddress((void**)&pK, g_K);
    cudaGetSymbolAddress((void**)&pV, g_V);

    build_weights<<<(NW + 255) / 256, 256>>>(cpq, cpk, cpv, cpo, ncp);
    split_x<<<(MROWS * HID / 4 + 255) / 256, 256>>>(x);

    cudaFuncSetAttribute(gemm_hmma, cudaFuncAttributeMaxDynamicSharedMemorySize,
                         GEMM_SMEM);
    dim3 gg(HID / 256, MROWS / 128);
    gemm_hmma<<<gg, 512, GEMM_SMEM>>>(pXh, pXl, pWh + 0 * (size_t)NW, pWl + 0 * (size_t)NW, pQ);
    gemm_hmma<<<gg, 512, GEMM_SMEM>>>(pXh, pXl, pWh + 1 * (size_t)NW, pWl + 1 * (size_t)NW, pK);
    gemm_hmma<<<gg, 512, GEMM_SMEM>>>(pXh, pXl, pWh + 2 * (size_t)NW, pWl + 2 * (size_t)NW, pV);

    cudaFuncSetAttribute(flash_hmma, cudaFuncAttributeMaxDynamicSharedMemorySize,
                         FL_SMEM);
    flash_hmma<<<dim3(SQ / 128, NHEAD, NB), 256, FL_SMEM>>>(pQ, pK, pV);

    gemm_hmma<<<gg, 512, GEMM_SMEM>>>(pAh, pAl, pWh + 3 * (size_t)NW, pWl + 3 * (size_t)NW, out);
}

// round 9
// speedup vs baseline: 1.0329x; 1.0039x over previous
#include <cuda_runtime.h>
#include <cuda_bf16.h>
#include <math.h>
#include <stdint.h>

#define HID   2048
#define NB    2
#define SQ    2048
#define NHEAD 16
#define HD    128
#define MROWS (NB * SQ)        /* 4096 */
#define NW    (HID * HID)      /* 4194304 */
#define KDIM  2048

/* ---------------- scratch (device globals; no allocation allowed) -------- */
__device__ __nv_bfloat16 g_Wh[4][NW];
__device__ __nv_bfloat16 g_Wl[4][NW];
__device__ __nv_bfloat16 g_Xh[MROWS * HID];
__device__ __nv_bfloat16 g_Xl[MROWS * HID];
__device__ __nv_bfloat16 g_Ah[MROWS * HID];
__device__ __nv_bfloat16 g_Al[MROWS * HID];
__device__ float g_Q[MROWS * HID];
__device__ float g_K[MROWS * HID];
__device__ float g_V[MROWS * HID];

__device__ __forceinline__ uint32_t smem_u32(const void* p) {
    uint32_t a;
    asm("{ .reg .u64 t; cvta.to.shared.u64 t, %1; cvt.u32.u64 %0, t; }"
        : "=r"(a) : "l"(p));
    return a;
}
__device__ __forceinline__ void ldm_x4(uint32_t* r, uint32_t addr) {
    asm volatile("ldmatrix.sync.aligned.m8n8.x4.shared.b16 {%0,%1,%2,%3}, [%4];"
                 : "=r"(r[0]), "=r"(r[1]), "=r"(r[2]), "=r"(r[3]) : "r"(addr));
}
__device__ __forceinline__ void mma_bf16(float* d, const uint32_t* a,
                                         uint32_t b0, uint32_t b1) {
    asm volatile("mma.sync.aligned.m16n8k16.row.col.f32.bf16.bf16.f32 "
                 "{%0,%1,%2,%3},{%4,%5,%6,%7},{%8,%9},{%0,%1,%2,%3};"
                 : "+f"(d[0]), "+f"(d[1]), "+f"(d[2]), "+f"(d[3])
                 : "r"(a[0]), "r"(a[1]), "r"(a[2]), "r"(a[3]), "r"(b0), "r"(b1));
}
__device__ __forceinline__ void split4(float4 v, uint2& hi, uint2& lo) {
    __nv_bfloat162 h0 = __float22bfloat162_rn(make_float2(v.x, v.y));
    __nv_bfloat162 h1 = __float22bfloat162_rn(make_float2(v.z, v.w));
    float2 f0 = __bfloat1622float2(h0), f1 = __bfloat1622float2(h1);
    __nv_bfloat162 l0 = __float22bfloat162_rn(make_float2(v.x - f0.x, v.y - f0.y));
    __nv_bfloat162 l1 = __float22bfloat162_rn(make_float2(v.z - f1.x, v.w - f1.y));
    hi = make_uint2(*(uint32_t*)&h0, *(uint32_t*)&h1);
    lo = make_uint2(*(uint32_t*)&l0, *(uint32_t*)&l1);
}
__device__ __forceinline__ uint32_t pack_hi(float a, float b) {
    __nv_bfloat162 h = __float22bfloat162_rn(make_float2(a, b));
    return *(uint32_t*)&h;
}
__device__ __forceinline__ uint32_t pack_lo(float a, float b, uint32_t hi) {
    float2 f = __bfloat1622float2(*(__nv_bfloat162*)&hi);
    __nv_bfloat162 l = __float22bfloat162_rn(make_float2(a - f.x, b - f.y));
    return *(uint32_t*)&l;
}
__device__ __forceinline__ void cp16(uint32_t smem, const void* g) {
    asm volatile("cp.async.cg.shared.global [%0], [%1], 16;"
                 :: "r"(smem), "l"(g) : "memory");
}
__device__ __forceinline__ void cp_commit() {
    asm volatile("cp.async.commit_group;" ::: "memory");
}
template <int N>
__device__ __forceinline__ void cp_wait() {
    asm volatile("cp.async.wait_group %0;" :: "n"(N) : "memory");
}

/* ---------------- weight reconstruction -> bf16 hi/lo -------------------- */
__global__ void build_weights(const float* __restrict__ cpq,
                              const float* __restrict__ cpk,
                              const float* __restrict__ cpv,
                              const float* __restrict__ cpo,
                              int ncp) {
    int i = blockIdx.x * 256 + threadIdx.x;
    if (i >= NW) return;
    const float dT = 1.0f / (float)(NW - 1);
    const float dX = 1.0f / (float)(ncp - 1);
    float t = (float)i * dT;
    int j = (int)((double)t * (double)(ncp - 1));
    if (j > ncp - 2) j = ncp - 2;
    if (j < 0) j = 0;
    while (j < ncp - 2 && (float)(j + 1) * dX <= t) j++;
    while (j > 0 && (float)j * dX > t) j--;
    float x0 = (float)j * dX;
    float x1 = (float)(j + 1) * dX;
    float f  = (t - x0) / (x1 - x0);
    const float* cps[4] = {cpq, cpk, cpv, cpo};
#pragma unroll
    for (int w = 0; w < 4; w++) {
        float a = cps[w][j];
        float val = fmaf(cps[w][j + 1] - a, f, a);
        __nv_bfloat16 hb = __float2bfloat16_rn(val);
        g_Wh[w][i] = hb;
        g_Wl[w][i] = __float2bfloat16_rn(val - __bfloat162float(hb));
    }
}

/* ---------------- split hidden_states -> bf16 hi/lo ---------------------- */
__global__ void split_x(const float* __restrict__ x) {
    int i = blockIdx.x * 256 + threadIdx.x;
    if (i >= MROWS * HID / 4) return;
    float4 v = *(const float4*)(x + 4 * (size_t)i);
    uint2 hi, lo; split4(v, hi, lo);
    *(uint2*)(g_Xh + 4 * (size_t)i) = hi;
    *(uint2*)(g_Xl + 4 * (size_t)i) = lo;
}

/* ====== bf16x3 HMMA GEMM, CTA 128x128, 256 thr, warp 64x32, 2 CTA/SM ===== */
#define KC      32
#define NCHUNK  (KDIM / KC)
#define SA      40                      /* halfwords per smem row (80 B)    */
#define OFF_AH  0
#define OFF_AL  (128 * SA)
#define OFF_BH  (2 * 128 * SA)
#define OFF_BL  (3 * 128 * SA)
#define STG_HW  (4 * 128 * SA)          /* 20480 halfwords                  */
#define STG_B   (STG_HW * 2)            /* 40960 B                          */
#define GEMM_SMEM (2 * STG_B)           /* 81920 B -> 2 CTAs/SM             */

__global__ void __launch_bounds__(256, 2) gemm_hmma(const __nv_bfloat16* __restrict__ Ah,
                                                    const __nv_bfloat16* __restrict__ Al,
                                                    const __nv_bfloat16* __restrict__ Bh,
                                                    const __nv_bfloat16* __restrict__ Bl,
                                                    float* __restrict__ C) {
    extern __shared__ char shg[];
    const uint32_t sb = smem_u32(shg);
    const int tid = threadIdx.x;
    const int lane = tid & 31, wid = tid >> 5;
    const int warp_m = wid >> 2;              /* 0..1 : 64-row block        */
    const int warp_n = wid & 3;               /* 0..3 : 32-col block        */
    const int m0 = blockIdx.y * 128, n0 = blockIdx.x * 128;

    /* cp.async coords: rows 0..63 (+64 in second copy), 4 thr per row */
    const int rA = tid >> 2;                  /* 0..63                      */
    const int cA = (tid & 3) << 3;            /* bf16 col 0,8,16,24         */
    const __nv_bfloat16* gAh = Ah + (size_t)(m0 + rA) * KDIM + cA;
    const __nv_bfloat16* gAl = Al + (size_t)(m0 + rA) * KDIM + cA;
    const __nv_bfloat16* gBh = Bh + (size_t)(n0 + rA) * KDIM + cA;
    const __nv_bfloat16* gBl = Bl + (size_t)(n0 + rA) * KDIM + cA;
    const size_t rowskip = (size_t)64 * KDIM;
    const uint32_t d0 = sb + (uint32_t)(rA * SA + cA) * 2;
    const uint32_t d1 = d0 + (uint32_t)(64 * SA) * 2;

    float acc[4][4][4];
#pragma unroll
    for (int i = 0; i < 4; i++)
#pragma unroll
        for (int j = 0; j < 4; j++)
#pragma unroll
            for (int q = 0; q < 4; q++) acc[i][j][q] = 0.0f;

    const int rowA = lane & 15, colA8 = (lane >= 16) ? 8 : 0;
    const int rowB = (lane & 7) + ((lane >= 16) ? 8 : 0);
    const int colB8 = (lane & 8) ? 8 : 0;
    const uint32_t aoff = (uint32_t)((warp_m * 64 + rowA) * SA + colA8) * 2;
    const uint32_t boff = (uint32_t)((warp_n * 32 + rowB) * SA + colB8) * 2;

    /* prologue: chunk 0 -> stage 0 */
    {
        cp16(d0 + OFF_AH * 2, gAh);            cp16(d1 + OFF_AH * 2, gAh + rowskip);
        cp16(d0 + OFF_AL * 2, gAl);            cp16(d1 + OFF_AL * 2, gAl + rowskip);
        cp16(d0 + OFF_BH * 2, gBh);            cp16(d1 + OFF_BH * 2, gBh + rowskip);
        cp16(d0 + OFF_BL * 2, gBl);            cp16(d1 + OFF_BL * 2, gBl + rowskip);
        cp_commit();
    }

    for (int c = 0; c < NCHUNK; c++) {
        cp_wait<0>();
        __syncthreads();
        if (c + 1 < NCHUNK) {
            const uint32_t st = ((c + 1) & 1) * STG_B;
            const int kc = (c + 1) * KC;
            cp16(d0 + st + OFF_AH * 2, gAh + kc);
            cp16(d1 + st + OFF_AH * 2, gAh + kc + rowskip);
            cp16(d0 + st + OFF_AL * 2, gAl + kc);
            cp16(d1 + st + OFF_AL * 2, gAl + kc + rowskip);
            cp16(d0 + st + OFF_BH * 2, gBh + kc);
            cp16(d1 + st + OFF_BH * 2, gBh + kc + rowskip);
            cp16(d0 + st + OFF_BL * 2, gBl + kc);
            cp16(d1 + st + OFF_BL * 2, gBl + kc + rowskip);
            cp_commit();
        }

        const uint32_t stg = sb + (c & 1) * STG_B;
        const uint32_t tAh = stg + OFF_AH * 2, tAl = stg + OFF_AL * 2;
        const uint32_t tBh = stg + OFF_BH * 2, tBl = stg + OFF_BL * 2;
#pragma unroll
        for (int ks = 0; ks < 2; ks++) {
            const uint32_t ksoff = (uint32_t)(ks * 16) * 2;
            uint32_t ah[4][4], al[4][4];
#pragma unroll
            for (int mt = 0; mt < 4; mt++) {
                ldm_x4(ah[mt], tAh + aoff + ksoff + (uint32_t)(mt * 16 * SA) * 2);
                ldm_x4(al[mt], tAl + aoff + ksoff + (uint32_t)(mt * 16 * SA) * 2);
            }
#pragma unroll
            for (int g = 0; g < 2; g++) {
                uint32_t bh[4], bl[4];
                ldm_x4(bh, tBh + boff + ksoff + (uint32_t)(g * 16 * SA) * 2);
                ldm_x4(bl, tBl + boff + ksoff + (uint32_t)(g * 16 * SA) * 2);
#pragma unroll
                for (int mt = 0; mt < 4; mt++) {
                    mma_bf16(acc[mt][2 * g],     ah[mt], bh[0], bh[1]);
                    mma_bf16(acc[mt][2 * g + 1], ah[mt], bh[2], bh[3]);
                }
#pragma unroll
                for (int mt = 0; mt < 4; mt++) {
                    mma_bf16(acc[mt][2 * g],     ah[mt], bl[0], bl[1]);
                    mma_bf16(acc[mt][2 * g + 1], ah[mt], bl[2], bl[3]);
                }
#pragma unroll
                for (int mt = 0; mt < 4; mt++) {
                    mma_bf16(acc[mt][2 * g],     al[mt], bh[0], bh[1]);
                    mma_bf16(acc[mt][2 * g + 1], al[mt], bh[2], bh[3]);
                }
            }
        }
    }

    const int rowg = lane >> 2, colg = (lane & 3) * 2;
#pragma unroll
    for (int mt = 0; mt < 4; mt++) {
#pragma unroll
        for (int nt = 0; nt < 4; nt++) {
            int r = m0 + warp_m * 64 + mt * 16 + rowg;
            int cc = n0 + warp_n * 32 + nt * 8 + colg;
            *(float2*)(C + (size_t)r * KDIM + cc) =
                make_float2(acc[mt][nt][0], acc[mt][nt][1]);
            *(float2*)(C + (size_t)(r + 8) * KDIM + cc) =
                make_float2(acc[mt][nt][2], acc[mt][nt][3]);
        }
    }
}

/* ========== bf16x3 HMMA causal flash attention =========================== */
#define FKS 136
#define FVS 72
#define OFF_QH 0
#define OFF_QL (128 * FKS)
#define OFF_KH (2 * 128 * FKS)
#define OFF_KL (OFF_KH + 64 * FKS)
#define OFF_VH (OFF_KL + 64 * FKS)
#define OFF_VL (OFF_VH + 128 * FVS)
#define FL_SMEM ((OFF_VL + 128 * FVS) * 2)

__global__ void __launch_bounds__(256, 1) flash_hmma(const float* __restrict__ Q,
                                                     const float* __restrict__ Km,
                                                     const float* __restrict__ Vm) {
    extern __shared__ char shf[];
    __nv_bfloat16* s = (__nv_bfloat16*)shf;
    const uint32_t sb = smem_u32(shf);
    const int tid = threadIdx.x, lane = tid & 31, wid = tid >> 5;
    const int qb = blockIdx.x, h = blockIdx.y, b = blockIdx.z;
    const int q0 = qb * 128;
    const int wm0 = wid * 16;
    const float scale = 0.08838834764831845f;

    const float* Qg = Q + (size_t)(b * SQ + q0) * HID + h * HD;
#pragma unroll
    for (int it = 0; it < 16; it++) {
        int idx = tid + it * 256;
        int r = idx >> 5, c4 = (idx & 31) << 2;
        float4 v = *(const float4*)(Qg + (size_t)r * HID + c4);
        uint2 hi, lo; split4(v, hi, lo);
        *(uint2*)(s + OFF_QH + r * FKS + c4) = hi;
        *(uint2*)(s + OFF_QL + r * FKS + c4) = lo;
    }

    const uint32_t aBaseH = sb + 2u * (OFF_QH + (wm0 + (lane & 15)) * FKS + ((lane >> 4) << 3));
    const uint32_t aBaseL = sb + 2u * (OFF_QL + (wm0 + (lane & 15)) * FKS + ((lane >> 4) << 3));
    const int krow = (lane & 7) + ((lane >> 4) << 3);
    const uint32_t kBaseH = sb + 2u * (OFF_KH + krow * FKS + (lane & 8));
    const uint32_t kBaseL = sb + 2u * (OFF_KL + krow * FKS + (lane & 8));
    const uint32_t vBaseH = sb + 2u * (OFF_VH + krow * FVS + (lane & 8));
    const uint32_t vBaseL = sb + 2u * (OFF_VL + krow * FVS + (lane & 8));

    float acc_o[16][4];
#pragma unroll
    for (int i = 0; i < 16; i++)
#pragma unroll
        for (int j = 0; j < 4; j++) acc_o[i][j] = 0.0f;
    float m0r = -1e30f, m1r = -1e30f, l0r = 0.0f, l1r = 0.0f;

    const int kb_max = 2 * qb + 1;
    const int r0g = q0 + wm0 + (lane >> 2);
    const int r1g = r0g + 8;

    for (int kb = 0; kb <= kb_max; kb++) {
        const int k0 = kb * 64;
        __syncthreads();
        const float* Kg = Km + (size_t)(b * SQ + k0) * HID + h * HD;
#pragma unroll
        for (int it = 0; it < 8; it++) {
            int idx = tid + it * 256;
            int r = idx >> 5, c4 = (idx & 31) << 2;
            float4 v = *(const float4*)(Kg + (size_t)r * HID + c4);
            uint2 hi, lo; split4(v, hi, lo);
            *(uint2*)(s + OFF_KH + r * FKS + c4) = hi;
            *(uint2*)(s + OFF_KL + r * FKS + c4) = lo;
        }
        const float* Vg = Vm + (size_t)(b * SQ + k0) * HID + h * HD;
#pragma unroll
        for (int it = 0; it < 8; it++) {
            int idx = tid + it * 256;
            int r = idx & 63, c4 = (idx >> 6) << 2;
            float4 v = *(const float4*)(Vg + (size_t)r * HID + c4);
            float e[4] = {v.x, v.y, v.z, v.w};
#pragma unroll
            for (int q = 0; q < 4; q++) {
                __nv_bfloat16 hb = __float2bfloat16_rn(e[q]);
                __nv_bfloat16 lb = __float2bfloat16_rn(e[q] - __bfloat162float(hb));
                s[OFF_VH + (c4 + q) * FVS + r] = hb;
                s[OFF_VL + (c4 + q) * FVS + r] = lb;
            }
        }
        __syncthreads();

        if (k0 > q0 + wm0) continue;

        float accs[8][4];
#pragma unroll
        for (int i = 0; i < 8; i++)
#pragma unroll
            for (int j = 0; j < 4; j++) accs[i][j] = 0.0f;
#pragma unroll
        for (int ks = 0; ks < 8; ks++) {
            uint32_t ah[4], al[4];
            ldm_x4(ah, aBaseH + ks * 32);
            ldm_x4(al, aBaseL + ks * 32);
            uint32_t bh[4][4], bl[4][4];
#pragma unroll
            for (int ng = 0; ng < 4; ng++) {
                ldm_x4(bh[ng], kBaseH + (uint32_t)(ng * 16 * FKS) * 2 + ks * 32);
                ldm_x4(bl[ng], kBaseL + (uint32_t)(ng * 16 * FKS) * 2 + ks * 32);
            }
#pragma unroll
            for (int ng = 0; ng < 4; ng++) {
                mma_bf16(accs[2 * ng],     ah, bh[ng][0], bh[ng][1]);
                mma_bf16(accs[2 * ng + 1], ah, bh[ng][2], bh[ng][3]);
            }
#pragma unroll
            for (int ng = 0; ng < 4; ng++) {
                mma_bf16(accs[2 * ng],     ah, bl[ng][0], bl[ng][1]);
                mma_bf16(accs[2 * ng + 1], ah, bl[ng][2], bl[ng][3]);
            }
#pragma unroll
            for (int ng = 0; ng < 4; ng++) {
                mma_bf16(accs[2 * ng],     al, bh[ng][0], bh[ng][1]);
                mma_bf16(accs[2 * ng + 1], al, bh[ng][2], bh[ng][3]);
            }
        }

#pragma unroll
        for (int nt = 0; nt < 8; nt++) {
            int cb = k0 + nt * 8 + (lane & 3) * 2;
            accs[nt][0] = accs[nt][0] * scale + ((cb     > r0g) ? -1e9f : 0.0f);
            accs[nt][1] = accs[nt][1] * scale + ((cb + 1 > r0g) ? -1e9f : 0.0f);
            accs[nt][2] = accs[nt][2] * scale + ((cb     > r1g) ? -1e9f : 0.0f);
            accs[nt][3] = accs[nt][3] * scale + ((cb + 1 > r1g) ? -1e9f : 0.0f);
        }

        float mx0 = -1e30f, mx1 = -1e30f;
#pragma unroll
        for (int nt = 0; nt < 8; nt++) {
            mx0 = fmaxf(mx0, fmaxf(accs[nt][0], accs[nt][1]));
            mx1 = fmaxf(mx1, fmaxf(accs[nt][2], accs[nt][3]));
        }
        mx0 = fmaxf(mx0, __shfl_xor_sync(0xffffffffu, mx0, 1));
        mx0 = fmaxf(mx0, __shfl_xor_sync(0xffffffffu, mx0, 2));
        mx1 = fmaxf(mx1, __shfl_xor_sync(0xffffffffu, mx1, 1));
        mx1 = fmaxf(mx1, __shfl_xor_sync(0xffffffffu, mx1, 2));
        float mn0 = fmaxf(m0r, mx0), mn1 = fmaxf(m1r, mx1);
        float al0 = __expf(m0r - mn0), al1 = __expf(m1r - mn1);
        m0r = mn0; m1r = mn1;
        float rs0 = 0.0f, rs1 = 0.0f;
#pragma unroll
        for (int nt = 0; nt < 8; nt++) {
            accs[nt][0] = __expf(accs[nt][0] - mn0);
            accs[nt][1] = __expf(accs[nt][1] - mn0);
            accs[nt][2] = __expf(accs[nt][2] - mn1);
            accs[nt][3] = __expf(accs[nt][3] - mn1);
            rs0 += accs[nt][0] + accs[nt][1];
            rs1 += accs[nt][2] + accs[nt][3];
        }
        rs0 += __shfl_xor_sync(0xffffffffu, rs0, 1);
        rs0 += __shfl_xor_sync(0xffffffffu, rs0, 2);
        rs1 += __shfl_xor_sync(0xffffffffu, rs1, 1);
        rs1 += __shfl_xor_sync(0xffffffffu, rs1, 2);
        l0r = l0r * al0 + rs0;
        l1r = l1r * al1 + rs1;
#pragma unroll
        for (int i = 0; i < 16; i++) {
            acc_o[i][0] *= al0; acc_o[i][1] *= al0;
            acc_o[i][2] *= al1; acc_o[i][3] *= al1;
        }

        uint32_t ph[4][4], pl[4][4];
#pragma unroll
        for (int kk = 0; kk < 4; kk++) {
            int n0t = 2 * kk, n1t = 2 * kk + 1;
            ph[kk][0] = pack_hi(accs[n0t][0], accs[n0t][1]);
            pl[kk][0] = pack_lo(accs[n0t][0], accs[n0t][1], ph[kk][0]);
            ph[kk][1] = pack_hi(accs[n0t][2], accs[n0t][3]);
            pl[kk][1] = pack_lo(accs[n0t][2], accs[n0t][3], ph[kk][1]);
            ph[kk][2] = pack_hi(accs[n1t][0], accs[n1t][1]);
            pl[kk][2] = pack_lo(accs[n1t][0], accs[n1t][1], ph[kk][2]);
            ph[kk][3] = pack_hi(accs[n1t][2], accs[n1t][3]);
            pl[kk][3] = pack_lo(accs[n1t][2], accs[n1t][3], ph[kk][3]);
        }

#pragma unroll
        for (int kk = 0; kk < 4; kk++) {
#pragma unroll
            for (int gb = 0; gb < 8; gb += 4) {
                uint32_t vh[4][4], vl[4][4];
#pragma unroll
                for (int g = 0; g < 4; g++) {
                    ldm_x4(vh[g], vBaseH + (uint32_t)((gb + g) * 16 * FVS) * 2 + kk * 32);
                    ldm_x4(vl[g], vBaseL + (uint32_t)((gb + g) * 16 * FVS) * 2 + kk * 32);
                }
#pragma unroll
                for (int g = 0; g < 4; g++) {
                    mma_bf16(acc_o[2 * (gb + g)],     ph[kk], vh[g][0], vh[g][1]);
                    mma_bf16(acc_o[2 * (gb + g) + 1], ph[kk], vh[g][2], vh[g][3]);
                }
#pragma unroll
                for (int g = 0; g < 4; g++) {
                    mma_bf16(acc_o[2 * (gb + g)],     ph[kk], vl[g][0], vl[g][1]);
                    mma_bf16(acc_o[2 * (gb + g) + 1], ph[kk], vl[g][2], vl[g][3]);
                }
#pragma unroll
                for (int g = 0; g < 4; g++) {
                    mma_bf16(acc_o[2 * (gb + g)],     pl[kk], vh[g][0], vh[g][1]);
                    mma_bf16(acc_o[2 * (gb + g) + 1], pl[kk], vh[g][2], vh[g][3]);
                }
            }
        }
    }

    float inv0 = 1.0f / l0r, inv1 = 1.0f / l1r;
    size_t base0 = (size_t)(b * SQ + r0g) * HID + h * HD;
    size_t base1 = base0 + (size_t)8 * HID;
#pragma unroll
    for (int nto = 0; nto < 16; nto++) {
        int c = nto * 8 + (lane & 3) * 2;
        float v0 = acc_o[nto][0] * inv0, v1 = acc_o[nto][1] * inv0;
        uint32_t hw = pack_hi(v0, v1);
        *(uint32_t*)(g_Ah + base0 + c) = hw;
        *(uint32_t*)(g_Al + base0 + c) = pack_lo(v0, v1, hw);
        float v2 = acc_o[nto][2] * inv1, v3 = acc_o[nto][3] * inv1;
        hw = pack_hi(v2, v3);
        *(uint32_t*)(g_Ah + base1 + c) = hw;
        *(uint32_t*)(g_Al + base1 + c) = pack_lo(v2, v3, hw);
    }
}

/* ---------------- launcher ---------------------------------------------- */
extern "C" void kernel_launch(void* const* d_in, const int* in_sizes, int n_in,
                              void* d_out, int out_size) {
    (void)n_in; (void)out_size;
    const float* x   = (const float*)d_in[0];
    const float* cpq = (const float*)d_in[1];
    const float* cpk = (const float*)d_in[2];
    const float* cpv = (const float*)d_in[3];
    const float* cpo = (const float*)d_in[4];
    float* out = (float*)d_out;
    int ncp = in_sizes[1];

    __nv_bfloat16 *pWh, *pWl, *pXh, *pXl, *pAh, *pAl;
    float *pQ, *pK, *pV;
    cudaGetSymbolAddress((void**)&pWh, g_Wh);
    cudaGetSymbolAddress((void**)&pWl, g_Wl);
    cudaGetSymbolAddress((void**)&pXh, g_Xh);
    cudaGetSymbolAddress((void**)&pXl, g_Xl);
    cudaGetSymbolAddress((void**)&pAh, g_Ah);
    cudaGetSymbolAddress((void**)&pAl, g_Al);
    cudaGetSymbolAddress((void**)&pQ, g_Q);
    cudaGetSymbolAddress((void**)&pK, g_K);
    cudaGetSymbolAddress((void**)&pV, g_V);

    build_weights<<<(NW + 255) / 256, 256>>>(cpq, cpk, cpv, cpo, ncp);
    split_x<<<(MROWS * HID / 4 + 255) / 256, 256>>>(x);

    cudaFuncSetAttribute(gemm_hmma, cudaFuncAttributeMaxDynamicSharedMemorySize,
                         GEMM_SMEM);
    dim3 gg(HID / 128, MROWS / 128);
    gemm_hmma<<<gg, 256, GEMM_SMEM>>>(pXh, pXl, pWh + 0 * (size_t)NW, pWl + 0 * (size_t)NW, pQ);
    gemm_hmma<<<gg, 256, GEMM_SMEM>>>(pXh, pXl, pWh + 1 * (size_t)NW, pWl + 1 * (size_t)NW, pK);
    gemm_hmma<<<gg, 256, GEMM_SMEM>>>(pXh, pXl, pWh + 2 * (size_t)NW, pWl + 2 * (size_t)NW, pV);

    cudaFuncSetAttribute(flash_hmma, cudaFuncAttributeMaxDynamicSharedMemorySize,
                         FL_SMEM);
    flash_hmma<<<dim3(SQ / 128, NHEAD, NB), 256, FL_SMEM>>>(pQ, pK, pV);

    gemm_hmma<<<gg, 256, GEMM_SMEM>>>(pAh, pAl, pWh + 3 * (size_t)NW, pWl + 3 * (size_t)NW, out);
}